// round 2
// baseline (speedup 1.0000x reference)
#include <cuda_runtime.h>
#include <math.h>

#define BB 64
#define LL 512
#define HH 768
#define NN 50
#define OO 768
#define MTOT (BB*NN)   // 3200

// ---------------- scratch (device globals; no allocations allowed) ----------
__device__ float g_X[MTOT*HH];     // gathered + positional-encoded input
__device__ float g_Wh[MTOT*HH];    // Wh of current GAT layer
__device__ float g_H1[MTOT*HH];    // elu(gat1)
__device__ float g_Hres[MTOT*HH];  // elu(gat2) + X
__device__ float g_T[MTOT*HH];     // Hres@Wa + ba
__device__ float g_att[BB*NN*NN];  // attention matrices
__device__ float g_D[BB*HH];       // pooled dialogue vectors

// ---------------- 1) gather + sinusoidal PE --------------------------------
__global__ void gather_pe_kernel(const float* __restrict__ emb,
                                 const int* __restrict__ ids)
{
    int bn = blockIdx.x;            // 0..3199
    int b = bn / NN, n = bn % NN;
    int h = threadIdx.x * 4;        // 192 threads * 4 = 768
    int id = ids[bn];
    float4 e = *(const float4*)(emb + ((size_t)b * LL + id) * HH + h);
    const float c = -logf(10000.0f) / (float)HH;
    float d0 = expf((float)h * c);
    float d1 = expf((float)(h + 2) * c);
    float a0 = (float)n * d0, a1 = (float)n * d1;
    e.x += sinf(a0); e.y += cosf(a0);
    e.z += sinf(a1); e.w += cosf(a1);
    *(float4*)(g_X + (size_t)bn * HH + h) = e;
}

// ---------------- 2) SGEMM: C[M,768] = A[M,768] @ W[768,768] + bias --------
__global__ __launch_bounds__(256, 2) void sgemm768(
    const float* __restrict__ A, const float* __restrict__ W,
    const float* __restrict__ bias, float* __restrict__ C, int M)
{
    __shared__ float As[8][128];
    __shared__ float Bs[8][128];
    const int tid = threadIdx.x;
    const int bm = blockIdx.y * 128, bn = blockIdx.x * 128;
    const int tx = tid & 15, ty = tid >> 4;
    const int arow = tid >> 1, acol = (tid & 1) * 4;
    const int brow = tid >> 5, bcol = (tid & 31) * 4;
    const bool aval = (bm + arow) < M;
    const float* Ap = A + (size_t)(bm + arow) * HH + acol;
    const float* Wp = W + (size_t)brow * HH + bn + bcol;

    float acc[8][8];
    #pragma unroll
    for (int i = 0; i < 8; i++)
        #pragma unroll
        for (int j = 0; j < 8; j++) acc[i][j] = 0.f;

    for (int k0 = 0; k0 < HH; k0 += 8) {
        float4 av = aval ? *(const float4*)(Ap + k0) : make_float4(0.f, 0.f, 0.f, 0.f);
        float4 bv = *(const float4*)(Wp + (size_t)k0 * HH);
        __syncthreads();
        As[acol + 0][arow] = av.x;
        As[acol + 1][arow] = av.y;
        As[acol + 2][arow] = av.z;
        As[acol + 3][arow] = av.w;
        *(float4*)&Bs[brow][bcol] = bv;
        __syncthreads();
        #pragma unroll
        for (int k = 0; k < 8; k++) {
            float ar[8], br[8];
            *(float4*)&ar[0] = *(const float4*)&As[k][ty * 8];
            *(float4*)&ar[4] = *(const float4*)&As[k][ty * 8 + 4];
            *(float4*)&br[0] = *(const float4*)&Bs[k][tx * 8];
            *(float4*)&br[4] = *(const float4*)&Bs[k][tx * 8 + 4];
            #pragma unroll
            for (int i = 0; i < 8; i++)
                #pragma unroll
                for (int j = 0; j < 8; j++)
                    acc[i][j] = fmaf(ar[i], br[j], acc[i][j]);
        }
    }

    float bb[8];
    *(float4*)&bb[0] = *(const float4*)(bias + bn + tx * 8);
    *(float4*)&bb[4] = *(const float4*)(bias + bn + tx * 8 + 4);
    #pragma unroll
    for (int i = 0; i < 8; i++) {
        int row = bm + ty * 8 + i;
        if (row < M) {
            float4 o0, o1;
            o0.x = acc[i][0] + bb[0]; o0.y = acc[i][1] + bb[1];
            o0.z = acc[i][2] + bb[2]; o0.w = acc[i][3] + bb[3];
            o1.x = acc[i][4] + bb[4]; o1.y = acc[i][5] + bb[5];
            o1.z = acc[i][6] + bb[6]; o1.w = acc[i][7] + bb[7];
            *(float4*)(C + (size_t)row * HH + bn + tx * 8) = o0;
            *(float4*)(C + (size_t)row * HH + bn + tx * 8 + 4) = o1;
        }
    }
}

// ---------------- 3) GAT attention: masked softmax of leaky_relu scores ----
__global__ void gat_att_kernel(const float* __restrict__ Wh,
                               const float* __restrict__ a,
                               const float* __restrict__ ab,
                               const int* __restrict__ adj,
                               float* __restrict__ att)
{
    int b = blockIdx.x;
    int t = threadIdx.x, lane = t & 31, w = t >> 5;   // 8 warps
    __shared__ float asrc[NN], adst[NN];
    const float* whb = Wh + (size_t)b * NN * HH;

    for (int n = w; n < NN; n += 8) {
        const float4* row = (const float4*)(whb + (size_t)n * HH);
        float s1 = 0.f, s2 = 0.f;
        for (int c2 = lane; c2 < HH / 4; c2 += 32) {
            float4 x = row[c2];
            float4 u = ((const float4*)a)[c2];
            float4 v = ((const float4*)a)[HH / 4 + c2];
            s1 += x.x * u.x + x.y * u.y + x.z * u.z + x.w * u.w;
            s2 += x.x * v.x + x.y * v.y + x.z * v.z + x.w * v.w;
        }
        #pragma unroll
        for (int o = 16; o; o >>= 1) {
            s1 += __shfl_xor_sync(~0u, s1, o);
            s2 += __shfl_xor_sync(~0u, s2, o);
        }
        if (lane == 0) { asrc[n] = s1; adst[n] = s2; }
    }
    __syncthreads();

    float abv = *ab;
    const int* adjb = adj + b * NN * NN;
    for (int i = w; i < NN; i += 8) {
        float ai = asrc[i];
        // lane covers j = lane and j2 = lane+32
        int j2 = lane + 32;
        float v0 = ai + adst[lane] + abv;
        v0 = v0 >= 0.f ? v0 : 0.3f * v0;
        float e0 = (adjb[i * NN + lane] > 0) ? v0 : -1e30f;
        float e1 = -1e30f;
        if (j2 < NN) {
            float v1 = ai + adst[j2] + abv;
            v1 = v1 >= 0.f ? v1 : 0.3f * v1;
            e1 = (adjb[i * NN + j2] > 0) ? v1 : -1e30f;
        }
        float m = fmaxf(e0, e1);
        #pragma unroll
        for (int o = 16; o; o >>= 1) m = fmaxf(m, __shfl_xor_sync(~0u, m, o));
        float x0 = expf(e0 - m);
        float x1 = (j2 < NN) ? expf(e1 - m) : 0.f;
        float s = x0 + x1;
        #pragma unroll
        for (int o = 16; o; o >>= 1) s += __shfl_xor_sync(~0u, s, o);
        float inv = 1.f / s;
        att[((size_t)b * NN + i) * NN + lane] = x0 * inv;
        if (j2 < NN) att[((size_t)b * NN + i) * NN + j2] = x1 * inv;
    }
}

// ---------------- 4) apply attention: out = elu(att @ Wh) (+ residual) -----
__global__ __launch_bounds__(256) void gat_apply_kernel(
    const float* __restrict__ att, const float* __restrict__ Wh,
    const float* __restrict__ resid, float* __restrict__ out)
{
    int b = blockIdx.y, ch = blockIdx.x;       // 6 chunks of 128 cols
    __shared__ float att_s[NN * NN];           // 10 KB
    __shared__ float whs[NN][128];             // 25.6 KB
    int t = threadIdx.x;
    for (int idx = t; idx < NN * NN; idx += 256)
        att_s[idx] = att[(size_t)b * NN * NN + idx];
    const float* whb = Wh + (size_t)b * NN * HH + ch * 128;
    for (int idx = t; idx < NN * 32; idx += 256) {
        int r = idx >> 5, c = (idx & 31) * 4;
        *(float4*)&whs[r][c] = *(const float4*)(whb + (size_t)r * HH + c);
    }
    __syncthreads();
    int hl = t & 127, i0 = t >> 7;
    for (int i = i0; i < NN; i += 2) {
        float acc = 0.f;
        #pragma unroll
        for (int j = 0; j < NN; j++)
            acc = fmaf(att_s[i * NN + j], whs[j][hl], acc);
        float val = acc > 0.f ? acc : expm1f(acc);
        size_t off = ((size_t)b * NN + i) * HH + ch * 128 + hl;
        if (resid) val += resid[off];
        out[off] = val;
    }
}

// ---------------- 5) attention pooling over N utterances -------------------
__global__ void pool_kernel(const float* __restrict__ T,
                            const float* __restrict__ v,
                            const float* __restrict__ Hres,
                            float* __restrict__ D)
{
    int b = blockIdx.x;
    int t = threadIdx.x, lane = t & 31, w = t >> 5;
    __shared__ float sc[NN];
    for (int n = w; n < NN; n += 8) {
        const float4* row = (const float4*)(T + ((size_t)b * NN + n) * HH);
        float s = 0.f;
        for (int c2 = lane; c2 < HH / 4; c2 += 32) {
            float4 x = row[c2];
            float4 u = ((const float4*)v)[c2];
            s += tanhf(x.x) * u.x + tanhf(x.y) * u.y +
                 tanhf(x.z) * u.z + tanhf(x.w) * u.w;
        }
        #pragma unroll
        for (int o = 16; o; o >>= 1) s += __shfl_xor_sync(~0u, s, o);
        if (lane == 0) sc[n] = s;
    }
    __syncthreads();
    if (t == 0) {
        float m = -1e30f;
        for (int n = 0; n < NN; n++) m = fmaxf(m, sc[n]);
        float s = 0.f;
        for (int n = 0; n < NN; n++) { sc[n] = expf(sc[n] - m); s += sc[n]; }
        float inv = 1.f / s;
        for (int n = 0; n < NN; n++) sc[n] *= inv;
    }
    __syncthreads();
    for (int h = t; h < HH; h += 256) {
        float acc = 0.f;
        #pragma unroll 5
        for (int n = 0; n < NN; n++)
            acc = fmaf(sc[n], Hres[((size_t)b * NN + n) * HH + h], acc);
        D[(size_t)b * HH + h] = acc;
    }
}

// ---------------- launch ----------------------------------------------------
extern "C" void kernel_launch(void* const* d_in, const int* in_sizes, int n_in,
                              void* d_out, int out_size)
{
    const float* emb = (const float*)d_in[0];
    const int*   ids = (const int*)  d_in[1];
    const int*   adj = (const int*)  d_in[2];
    const float* W1  = (const float*)d_in[3];
    const float* b1  = (const float*)d_in[4];
    const float* a1  = (const float*)d_in[5];
    const float* ab1 = (const float*)d_in[6];
    const float* W2  = (const float*)d_in[7];
    const float* b2  = (const float*)d_in[8];
    const float* a2  = (const float*)d_in[9];
    const float* ab2 = (const float*)d_in[10];
    const float* Wa  = (const float*)d_in[11];
    const float* ba  = (const float*)d_in[12];
    const float* v   = (const float*)d_in[13];
    const float* Wl  = (const float*)d_in[14];
    const float* bl  = (const float*)d_in[15];
    float* out = (float*)d_out;

    void *pX, *pWh, *pH1, *pHres, *pT, *pAtt, *pD;
    cudaGetSymbolAddress(&pX, g_X);
    cudaGetSymbolAddress(&pWh, g_Wh);
    cudaGetSymbolAddress(&pH1, g_H1);
    cudaGetSymbolAddress(&pHres, g_Hres);
    cudaGetSymbolAddress(&pT, g_T);
    cudaGetSymbolAddress(&pAtt, g_att);
    cudaGetSymbolAddress(&pD, g_D);
    float* X    = (float*)pX;
    float* Wh   = (float*)pWh;
    float* H1   = (float*)pH1;
    float* Hres = (float*)pHres;
    float* T    = (float*)pT;
    float* Att  = (float*)pAtt;
    float* D    = (float*)pD;

    dim3 ggemm(HH / 128, (MTOT + 127) / 128);   // (6, 25)
    dim3 gfin(HH / 128, 1);                     // final GEMM M=64
    dim3 gapply(HH / 128, BB);                  // (6, 64)

    // 1) gather + PE
    gather_pe_kernel<<<MTOT, HH / 4>>>(emb, ids);
    // 2) Wh1 = X @ W1 + b1
    sgemm768<<<ggemm, 256>>>(X, W1, b1, Wh, MTOT);
    // 3) GAT layer 1 attention + apply (elu)
    gat_att_kernel<<<BB, 256>>>(Wh, a1, ab1, adj, Att);
    gat_apply_kernel<<<gapply, 256>>>(Att, Wh, nullptr, H1);
    // 4) Wh2 = H1 @ W2 + b2
    sgemm768<<<ggemm, 256>>>(H1, W2, b2, Wh, MTOT);
    // 5) GAT layer 2 attention + apply (elu + residual X)
    gat_att_kernel<<<BB, 256>>>(Wh, a2, ab2, adj, Att);
    gat_apply_kernel<<<gapply, 256>>>(Att, Wh, X, Hres);
    // 6) T = Hres @ Wa + ba
    sgemm768<<<ggemm, 256>>>(Hres, Wa, ba, T, MTOT);
    // 7) attention pooling -> D[64,768]
    pool_kernel<<<BB, 256>>>(T, v, Hres, D);
    // 8) out = D @ Wl + bl
    sgemm768<<<gfin, 256>>>(D, Wl, bl, out, BB);
}

// round 3
// speedup vs baseline: 1.0367x; 1.0367x over previous
#include <cuda_runtime.h>
#include <math.h>

#define BB 64
#define LL 512
#define HH 768
#define NN 50
#define OO 768
#define MTOT (BB*NN)   // 3200

// ---------------- scratch (device globals; no allocations allowed) ----------
__device__ float g_X[MTOT*HH];     // gathered + positional-encoded input
__device__ float g_Wh[MTOT*HH];    // Wh of current GAT layer
__device__ float g_H1[MTOT*HH];    // elu(gat1)
__device__ float g_Hres[MTOT*HH];  // elu(gat2) + X
__device__ float g_T[MTOT*HH];     // Hres@Wa + ba
__device__ float g_att[BB*NN*NN];  // attention matrices
__device__ float g_D[BB*HH];       // pooled dialogue vectors

// ---------------- 1) gather + sinusoidal PE --------------------------------
__global__ void gather_pe_kernel(const float* __restrict__ emb,
                                 const int* __restrict__ ids)
{
    int bn = blockIdx.x;            // 0..3199
    int b = bn / NN, n = bn % NN;
    int h = threadIdx.x * 4;        // 192 threads * 4 = 768
    int id = ids[bn];
    float4 e = *(const float4*)(emb + ((size_t)b * LL + id) * HH + h);
    const float c = -logf(10000.0f) / (float)HH;
    float d0 = expf((float)h * c);
    float d1 = expf((float)(h + 2) * c);
    float a0 = (float)n * d0, a1 = (float)n * d1;
    e.x += sinf(a0); e.y += cosf(a0);
    e.z += sinf(a1); e.w += cosf(a1);
    *(float4*)(g_X + (size_t)bn * HH + h) = e;
}

// ---------------- 2) SGEMM: C[M,768] = A[M,768] @ W[768,768] + bias --------
__global__ __launch_bounds__(256, 2) void sgemm768(
    const float* __restrict__ A, const float* __restrict__ W,
    const float* __restrict__ bias, float* __restrict__ C, int M)
{
    __shared__ float As[8][128];
    __shared__ float Bs[8][128];
    const int tid = threadIdx.x;
    const int bm = blockIdx.y * 128, bn = blockIdx.x * 128;
    const int tx = tid & 15, ty = tid >> 4;
    const int arow = tid >> 1, acol = (tid & 1) * 4;
    const int brow = tid >> 5, bcol = (tid & 31) * 4;
    const bool aval = (bm + arow) < M;
    const float* Ap = A + (size_t)(bm + arow) * HH + acol;
    const float* Wp = W + (size_t)brow * HH + bn + bcol;

    float acc[8][8];
    #pragma unroll
    for (int i = 0; i < 8; i++)
        #pragma unroll
        for (int j = 0; j < 8; j++) acc[i][j] = 0.f;

    for (int k0 = 0; k0 < HH; k0 += 8) {
        float4 av = aval ? *(const float4*)(Ap + k0) : make_float4(0.f, 0.f, 0.f, 0.f);
        float4 bv = *(const float4*)(Wp + (size_t)k0 * HH);
        __syncthreads();
        As[acol + 0][arow] = av.x;
        As[acol + 1][arow] = av.y;
        As[acol + 2][arow] = av.z;
        As[acol + 3][arow] = av.w;
        *(float4*)&Bs[brow][bcol] = bv;
        __syncthreads();
        #pragma unroll
        for (int k = 0; k < 8; k++) {
            float ar[8], br[8];
            *(float4*)&ar[0] = *(const float4*)&As[k][ty * 8];
            *(float4*)&ar[4] = *(const float4*)&As[k][ty * 8 + 4];
            *(float4*)&br[0] = *(const float4*)&Bs[k][tx * 8];
            *(float4*)&br[4] = *(const float4*)&Bs[k][tx * 8 + 4];
            #pragma unroll
            for (int i = 0; i < 8; i++)
                #pragma unroll
                for (int j = 0; j < 8; j++)
                    acc[i][j] = fmaf(ar[i], br[j], acc[i][j]);
        }
    }

    float bb[8];
    *(float4*)&bb[0] = *(const float4*)(bias + bn + tx * 8);
    *(float4*)&bb[4] = *(const float4*)(bias + bn + tx * 8 + 4);
    #pragma unroll
    for (int i = 0; i < 8; i++) {
        int row = bm + ty * 8 + i;
        if (row < M) {
            float4 o0, o1;
            o0.x = acc[i][0] + bb[0]; o0.y = acc[i][1] + bb[1];
            o0.z = acc[i][2] + bb[2]; o0.w = acc[i][3] + bb[3];
            o1.x = acc[i][4] + bb[4]; o1.y = acc[i][5] + bb[5];
            o1.z = acc[i][6] + bb[6]; o1.w = acc[i][7] + bb[7];
            *(float4*)(C + (size_t)row * HH + bn + tx * 8) = o0;
            *(float4*)(C + (size_t)row * HH + bn + tx * 8 + 4) = o1;
        }
    }
}

// ---------------- 3) GAT attention: masked softmax of leaky_relu scores ----
__global__ void gat_att_kernel(const float* __restrict__ Wh,
                               const float* __restrict__ a,
                               const float* __restrict__ ab,
                               const int* __restrict__ adj,
                               float* __restrict__ att)
{
    int b = blockIdx.x;
    int t = threadIdx.x, lane = t & 31, w = t >> 5;   // 8 warps
    __shared__ float asrc[NN], adst[NN];
    const float* whb = Wh + (size_t)b * NN * HH;

    for (int n = w; n < NN; n += 8) {
        const float4* row = (const float4*)(whb + (size_t)n * HH);
        float s1 = 0.f, s2 = 0.f;
        for (int c2 = lane; c2 < HH / 4; c2 += 32) {
            float4 x = row[c2];
            float4 u = ((const float4*)a)[c2];
            float4 v = ((const float4*)a)[HH / 4 + c2];
            s1 += x.x * u.x + x.y * u.y + x.z * u.z + x.w * u.w;
            s2 += x.x * v.x + x.y * v.y + x.z * v.z + x.w * v.w;
        }
        #pragma unroll
        for (int o = 16; o; o >>= 1) {
            s1 += __shfl_xor_sync(~0u, s1, o);
            s2 += __shfl_xor_sync(~0u, s2, o);
        }
        if (lane == 0) { asrc[n] = s1; adst[n] = s2; }
    }
    __syncthreads();

    float abv = *ab;
    const int* adjb = adj + b * NN * NN;
    for (int i = w; i < NN; i += 8) {
        float ai = asrc[i];
        // lane covers j = lane and j2 = lane+32
        int j2 = lane + 32;
        float v0 = ai + adst[lane] + abv;
        v0 = v0 >= 0.f ? v0 : 0.3f * v0;
        float e0 = (adjb[i * NN + lane] > 0) ? v0 : -1e30f;
        float e1 = -1e30f;
        if (j2 < NN) {
            float v1 = ai + adst[j2] + abv;
            v1 = v1 >= 0.f ? v1 : 0.3f * v1;
            e1 = (adjb[i * NN + j2] > 0) ? v1 : -1e30f;
        }
        float m = fmaxf(e0, e1);
        #pragma unroll
        for (int o = 16; o; o >>= 1) m = fmaxf(m, __shfl_xor_sync(~0u, m, o));
        float x0 = expf(e0 - m);
        float x1 = (j2 < NN) ? expf(e1 - m) : 0.f;
        float s = x0 + x1;
        #pragma unroll
        for (int o = 16; o; o >>= 1) s += __shfl_xor_sync(~0u, s, o);
        float inv = 1.f / s;
        att[((size_t)b * NN + i) * NN + lane] = x0 * inv;
        if (j2 < NN) att[((size_t)b * NN + i) * NN + j2] = x1 * inv;
    }
}

// ---------------- 4) apply attention: out = elu(att @ Wh) (+ residual) -----
__global__ __launch_bounds__(256) void gat_apply_kernel(
    const float* __restrict__ att, const float* __restrict__ Wh,
    const float* __restrict__ resid, float* __restrict__ out)
{
    int b = blockIdx.y, ch = blockIdx.x;       // 6 chunks of 128 cols
    __shared__ float att_s[NN * NN];           // 10 KB
    __shared__ float whs[NN][128];             // 25.6 KB
    int t = threadIdx.x;
    for (int idx = t; idx < NN * NN; idx += 256)
        att_s[idx] = att[(size_t)b * NN * NN + idx];
    const float* whb = Wh + (size_t)b * NN * HH + ch * 128;
    for (int idx = t; idx < NN * 32; idx += 256) {
        int r = idx >> 5, c = (idx & 31) * 4;
        *(float4*)&whs[r][c] = *(const float4*)(whb + (size_t)r * HH + c);
    }
    __syncthreads();
    int hl = t & 127, i0 = t >> 7;
    for (int i = i0; i < NN; i += 2) {
        float acc = 0.f;
        #pragma unroll
        for (int j = 0; j < NN; j++)
            acc = fmaf(att_s[i * NN + j], whs[j][hl], acc);
        float val = acc > 0.f ? acc : expm1f(acc);
        size_t off = ((size_t)b * NN + i) * HH + ch * 128 + hl;
        if (resid) val += resid[off];
        out[off] = val;
    }
}

// ---------------- 5) attention pooling over N utterances -------------------
__global__ void pool_kernel(const float* __restrict__ T,
                            const float* __restrict__ v,
                            const float* __restrict__ Hres,
                            float* __restrict__ D)
{
    int b = blockIdx.x;
    int t = threadIdx.x, lane = t & 31, w = t >> 5;
    __shared__ float sc[NN];
    for (int n = w; n < NN; n += 8) {
        const float4* row = (const float4*)(T + ((size_t)b * NN + n) * HH);
        float s = 0.f;
        for (int c2 = lane; c2 < HH / 4; c2 += 32) {
            float4 x = row[c2];
            float4 u = ((const float4*)v)[c2];
            s += tanhf(x.x) * u.x + tanhf(x.y) * u.y +
                 tanhf(x.z) * u.z + tanhf(x.w) * u.w;
        }
        #pragma unroll
        for (int o = 16; o; o >>= 1) s += __shfl_xor_sync(~0u, s, o);
        if (lane == 0) sc[n] = s;
    }
    __syncthreads();
    if (t == 0) {
        float m = -1e30f;
        for (int n = 0; n < NN; n++) m = fmaxf(m, sc[n]);
        float s = 0.f;
        for (int n = 0; n < NN; n++) { sc[n] = expf(sc[n] - m); s += sc[n]; }
        float inv = 1.f / s;
        for (int n = 0; n < NN; n++) sc[n] *= inv;
    }
    __syncthreads();
    for (int h = t; h < HH; h += 256) {
        float acc = 0.f;
        #pragma unroll 5
        for (int n = 0; n < NN; n++)
            acc = fmaf(sc[n], Hres[((size_t)b * NN + n) * HH + h], acc);
        D[(size_t)b * HH + h] = acc;
    }
}

// ---------------- launch ----------------------------------------------------
extern "C" void kernel_launch(void* const* d_in, const int* in_sizes, int n_in,
                              void* d_out, int out_size)
{
    const float* emb = (const float*)d_in[0];
    const int*   ids = (const int*)  d_in[1];
    const int*   adj = (const int*)  d_in[2];
    const float* W1  = (const float*)d_in[3];
    const float* b1  = (const float*)d_in[4];
    const float* a1  = (const float*)d_in[5];
    const float* ab1 = (const float*)d_in[6];
    const float* W2  = (const float*)d_in[7];
    const float* b2  = (const float*)d_in[8];
    const float* a2  = (const float*)d_in[9];
    const float* ab2 = (const float*)d_in[10];
    const float* Wa  = (const float*)d_in[11];
    const float* ba  = (const float*)d_in[12];
    const float* v   = (const float*)d_in[13];
    const float* Wl  = (const float*)d_in[14];
    const float* bl  = (const float*)d_in[15];
    float* out = (float*)d_out;

    void *pX, *pWh, *pH1, *pHres, *pT, *pAtt, *pD;
    cudaGetSymbolAddress(&pX, g_X);
    cudaGetSymbolAddress(&pWh, g_Wh);
    cudaGetSymbolAddress(&pH1, g_H1);
    cudaGetSymbolAddress(&pHres, g_Hres);
    cudaGetSymbolAddress(&pT, g_T);
    cudaGetSymbolAddress(&pAtt, g_att);
    cudaGetSymbolAddress(&pD, g_D);
    float* X    = (float*)pX;
    float* Wh   = (float*)pWh;
    float* H1   = (float*)pH1;
    float* Hres = (float*)pHres;
    float* T    = (float*)pT;
    float* Att  = (float*)pAtt;
    float* D    = (float*)pD;

    dim3 ggemm(HH / 128, (MTOT + 127) / 128);   // (6, 25)
    dim3 gfin(HH / 128, 1);                     // final GEMM M=64
    dim3 gapply(HH / 128, BB);                  // (6, 64)

    // 1) gather + PE
    gather_pe_kernel<<<MTOT, HH / 4>>>(emb, ids);
    // 2) Wh1 = X @ W1 + b1
    sgemm768<<<ggemm, 256>>>(X, W1, b1, Wh, MTOT);
    // 3) GAT layer 1 attention + apply (elu)
    gat_att_kernel<<<BB, 256>>>(Wh, a1, ab1, adj, Att);
    gat_apply_kernel<<<gapply, 256>>>(Att, Wh, nullptr, H1);
    // 4) Wh2 = H1 @ W2 + b2
    sgemm768<<<ggemm, 256>>>(H1, W2, b2, Wh, MTOT);
    // 5) GAT layer 2 attention + apply (elu + residual X)
    gat_att_kernel<<<BB, 256>>>(Wh, a2, ab2, adj, Att);
    gat_apply_kernel<<<gapply, 256>>>(Att, Wh, X, Hres);
    // 6) T = Hres @ Wa + ba
    sgemm768<<<ggemm, 256>>>(Hres, Wa, ba, T, MTOT);
    // 7) attention pooling -> D[64,768]
    pool_kernel<<<BB, 256>>>(T, v, Hres, D);
    // 8) out = D @ Wl + bl
    sgemm768<<<gfin, 256>>>(D, Wl, bl, out, BB);
}

// round 4
// speedup vs baseline: 2.0297x; 1.9579x over previous
#include <cuda_runtime.h>
#include <cuda_bf16.h>
#include <math.h>

#define BB 64
#define LL 512
#define HH 768
#define NN 50
#define OO 768
#define MTOT (BB*NN)   // 3200

// ---------------- scratch (device globals; no allocations allowed) ----------
__device__ float g_X[MTOT*HH];     // gathered + positional-encoded input
__device__ float g_Wh[MTOT*HH];    // Wh of current GAT layer
__device__ float g_H1[MTOT*HH];    // elu(gat1)
__device__ float g_Hres[MTOT*HH];  // elu(gat2) + X
__device__ float g_T[MTOT*HH];     // Hres@Wa + ba
__device__ float g_att[BB*NN*NN];  // attention matrices
__device__ float g_D[BB*HH];       // pooled dialogue vectors
// bf16 split buffers (A reused across GEMMs, W reused across GEMMs)
__device__ __nv_bfloat16 g_Ah[MTOT*HH];
__device__ __nv_bfloat16 g_Al[MTOT*HH];
__device__ __nv_bfloat16 g_Bh[HH*HH];
__device__ __nv_bfloat16 g_Bl[HH*HH];

// ---------------- 1) gather + sinusoidal PE --------------------------------
__global__ void gather_pe_kernel(const float* __restrict__ emb,
                                 const int* __restrict__ ids)
{
    int bn = blockIdx.x;            // 0..3199
    int b = bn / NN, n = bn % NN;
    int h = threadIdx.x * 4;        // 192 threads * 4 = 768
    int id = ids[bn];
    float4 e = *(const float4*)(emb + ((size_t)b * LL + id) * HH + h);
    const float c = -logf(10000.0f) / (float)HH;
    float d0 = expf((float)h * c);
    float d1 = expf((float)(h + 2) * c);
    float a0 = (float)n * d0, a1 = (float)n * d1;
    e.x += sinf(a0); e.y += cosf(a0);
    e.z += sinf(a1); e.w += cosf(a1);
    *(float4*)(g_X + (size_t)bn * HH + h) = e;
}

// ---------------- split fp32 -> bf16 hi + bf16 lo --------------------------
__global__ void split_bf16_kernel(const float* __restrict__ src,
                                  __nv_bfloat16* __restrict__ hi,
                                  __nv_bfloat16* __restrict__ lo, int n4)
{
    int i = blockIdx.x * blockDim.x + threadIdx.x;
    if (i >= n4) return;
    float4 v = ((const float4*)src)[i];
    __nv_bfloat16 h0 = __float2bfloat16(v.x);
    __nv_bfloat16 h1 = __float2bfloat16(v.y);
    __nv_bfloat16 h2 = __float2bfloat16(v.z);
    __nv_bfloat16 h3 = __float2bfloat16(v.w);
    __nv_bfloat16 l0 = __float2bfloat16(v.x - __bfloat162float(h0));
    __nv_bfloat16 l1 = __float2bfloat16(v.y - __bfloat162float(h1));
    __nv_bfloat16 l2 = __float2bfloat16(v.z - __bfloat162float(h2));
    __nv_bfloat16 l3 = __float2bfloat16(v.w - __bfloat162float(h3));
    __nv_bfloat162* H = (__nv_bfloat162*)hi;
    __nv_bfloat162* L = (__nv_bfloat162*)lo;
    H[2*i]   = __nv_bfloat162(h0, h1);
    H[2*i+1] = __nv_bfloat162(h2, h3);
    L[2*i]   = __nv_bfloat162(l0, l1);
    L[2*i+1] = __nv_bfloat162(l2, l3);
}

// ---------------- tensor-core GEMM (bf16x3 split, fp32 accum) --------------
// C[M,768] = A[M,768] @ W[768,768] + bias.  A,W provided as hi/lo bf16 pairs.
// CTA tile 128x128, warp tile 32x64, K-chunk 32, cp.async double buffer.
#define SA_IDX(st,sp,r,c) ((((st)*2+(sp))*128 + (r))*40 + (c))
#define SB_IDX(st,sp,r,c) (20480 + (((st)*2+(sp))*32 + (r))*136 + (c))
#define SMEM_BF16 (20480 + 17408)   // elems; *2 = 75776 bytes

#define CP16(dst, src) \
    asm volatile("cp.async.cg.shared.global [%0], [%1], 16;\n" :: "r"(dst), "l"(src))

__device__ __forceinline__ void ldsm4(unsigned* r, const void* p) {
    unsigned addr = (unsigned)__cvta_generic_to_shared(p);
    asm volatile("ldmatrix.sync.aligned.m8n8.x4.shared.b16 {%0,%1,%2,%3}, [%4];\n"
                 : "=r"(r[0]), "=r"(r[1]), "=r"(r[2]), "=r"(r[3]) : "r"(addr));
}
__device__ __forceinline__ void ldsm4t(unsigned* r, const void* p) {
    unsigned addr = (unsigned)__cvta_generic_to_shared(p);
    asm volatile("ldmatrix.sync.aligned.m8n8.x4.trans.shared.b16 {%0,%1,%2,%3}, [%4];\n"
                 : "=r"(r[0]), "=r"(r[1]), "=r"(r[2]), "=r"(r[3]) : "r"(addr));
}
__device__ __forceinline__ void mma16816(float* c, const unsigned* a, const unsigned* b) {
    asm volatile("mma.sync.aligned.m16n8k16.row.col.f32.bf16.bf16.f32 "
                 "{%0,%1,%2,%3}, {%4,%5,%6,%7}, {%8,%9}, {%0,%1,%2,%3};\n"
                 : "+f"(c[0]), "+f"(c[1]), "+f"(c[2]), "+f"(c[3])
                 : "r"(a[0]), "r"(a[1]), "r"(a[2]), "r"(a[3]),
                   "r"(b[0]), "r"(b[1]));
}

__global__ __launch_bounds__(256, 1) void gemm_bf16x3(
    const __nv_bfloat16* __restrict__ Ah, const __nv_bfloat16* __restrict__ Al,
    const __nv_bfloat16* __restrict__ Bh, const __nv_bfloat16* __restrict__ Bl,
    const float* __restrict__ bias, float* __restrict__ C, int M)
{
    extern __shared__ __nv_bfloat16 sm[];
    const int tid = threadIdx.x;
    const int lane = tid & 31, wid = tid >> 5;
    const int warp_m = wid >> 1, warp_n = wid & 1;
    const int bm = blockIdx.y * 128, bn = blockIdx.x * 128;

    const int ar = tid >> 2, ac = (tid & 3) * 8;    // A: 64 rows/pass, 4 col groups
    const int br = tid >> 4, bc = (tid & 15) * 8;   // B: 16 rows/pass, 16 col groups
    // clamp A rows so M<128 tiles never read OOB (values masked at store)
    const int rA0 = min(bm + ar, M - 1);
    const int rA1 = min(bm + ar + 64, M - 1);

    float acc[2][8][4] = {};

    const __nv_bfloat16* As[2] = {Ah, Al};
    const __nv_bfloat16* Bs[2] = {Bh, Bl};

    // ---- stage loader ----
    auto load_stage = [&](int st, int k0) {
        #pragma unroll
        for (int s = 0; s < 2; s++) {
            unsigned d0 = (unsigned)__cvta_generic_to_shared(&sm[SA_IDX(st, s, ar, ac)]);
            CP16(d0, As[s] + (size_t)rA0 * HH + k0 + ac);
            unsigned d1 = (unsigned)__cvta_generic_to_shared(&sm[SA_IDX(st, s, ar + 64, ac)]);
            CP16(d1, As[s] + (size_t)rA1 * HH + k0 + ac);
            unsigned e0 = (unsigned)__cvta_generic_to_shared(&sm[SB_IDX(st, s, br, bc)]);
            CP16(e0, Bs[s] + (size_t)(k0 + br) * HH + bn + bc);
            unsigned e1 = (unsigned)__cvta_generic_to_shared(&sm[SB_IDX(st, s, br + 16, bc)]);
            CP16(e1, Bs[s] + (size_t)(k0 + br + 16) * HH + bn + bc);
        }
        asm volatile("cp.async.commit_group;\n" ::: "memory");
    };

    load_stage(0, 0);
    const int lrow = lane & 15, lcol = (lane >> 4) * 8;

    for (int c = 0; c < HH / 32; c++) {
        if (c < HH / 32 - 1) {
            load_stage((c + 1) & 1, (c + 1) * 32);
            asm volatile("cp.async.wait_group 1;\n" ::: "memory");
        } else {
            asm volatile("cp.async.wait_group 0;\n" ::: "memory");
        }
        __syncthreads();
        const int st = c & 1;
        #pragma unroll
        for (int ks = 0; ks < 2; ks++) {
            const int kb = ks * 16;
            unsigned a[2][2][4];   // [split][mtile][4]
            #pragma unroll
            for (int mt = 0; mt < 2; mt++)
                #pragma unroll
                for (int s = 0; s < 2; s++)
                    ldsm4(a[s][mt], &sm[SA_IDX(st, s, warp_m * 32 + mt * 16 + lrow, kb + lcol)]);
            unsigned b[2][8][2];   // [split][ntile][2]
            #pragma unroll
            for (int g = 0; g < 4; g++)
                #pragma unroll
                for (int s = 0; s < 2; s++) {
                    unsigned r[4];
                    ldsm4t(r, &sm[SB_IDX(st, s, kb + lrow, warp_n * 64 + g * 16 + lcol)]);
                    b[s][2*g][0]   = r[0]; b[s][2*g][1]   = r[1];
                    b[s][2*g+1][0] = r[2]; b[s][2*g+1][1] = r[3];
                }
            #pragma unroll
            for (int mt = 0; mt < 2; mt++)
                #pragma unroll
                for (int nt = 0; nt < 8; nt++) {
                    mma16816(acc[mt][nt], a[0][mt], b[0][nt]);   // hi*hi
                    mma16816(acc[mt][nt], a[0][mt], b[1][nt]);   // hi*lo
                    mma16816(acc[mt][nt], a[1][mt], b[0][nt]);   // lo*hi
                }
        }
        __syncthreads();
    }

    // ---- epilogue: bias add, fp32 store ----
    const int er = bm + warp_m * 32 + (lane >> 2);
    const int ec = bn + warp_n * 64 + (lane & 3) * 2;
    #pragma unroll
    for (int mt = 0; mt < 2; mt++)
        #pragma unroll
        for (int nt = 0; nt < 8; nt++) {
            int r = er + mt * 16;
            int cc = ec + nt * 8;
            float b0 = bias[cc], b1 = bias[cc + 1];
            if (r < M) {
                C[(size_t)r * HH + cc]     = acc[mt][nt][0] + b0;
                C[(size_t)r * HH + cc + 1] = acc[mt][nt][1] + b1;
            }
            if (r + 8 < M) {
                C[(size_t)(r + 8) * HH + cc]     = acc[mt][nt][2] + b0;
                C[(size_t)(r + 8) * HH + cc + 1] = acc[mt][nt][3] + b1;
            }
        }
}

// ---------------- 3) GAT attention: masked softmax of leaky_relu scores ----
__global__ void gat_att_kernel(const float* __restrict__ Wh,
                               const float* __restrict__ a,
                               const float* __restrict__ ab,
                               const int* __restrict__ adj,
                               float* __restrict__ att)
{
    int b = blockIdx.x;
    int t = threadIdx.x, lane = t & 31, w = t >> 5;   // 8 warps
    __shared__ float asrc[NN], adst[NN];
    const float* whb = Wh + (size_t)b * NN * HH;

    for (int n = w; n < NN; n += 8) {
        const float4* row = (const float4*)(whb + (size_t)n * HH);
        float s1 = 0.f, s2 = 0.f;
        for (int c2 = lane; c2 < HH / 4; c2 += 32) {
            float4 x = row[c2];
            float4 u = ((const float4*)a)[c2];
            float4 v = ((const float4*)a)[HH / 4 + c2];
            s1 += x.x * u.x + x.y * u.y + x.z * u.z + x.w * u.w;
            s2 += x.x * v.x + x.y * v.y + x.z * v.z + x.w * v.w;
        }
        #pragma unroll
        for (int o = 16; o; o >>= 1) {
            s1 += __shfl_xor_sync(~0u, s1, o);
            s2 += __shfl_xor_sync(~0u, s2, o);
        }
        if (lane == 0) { asrc[n] = s1; adst[n] = s2; }
    }
    __syncthreads();

    float abv = *ab;
    const int* adjb = adj + b * NN * NN;
    for (int i = w; i < NN; i += 8) {
        float ai = asrc[i];
        int j2 = lane + 32;
        float v0 = ai + adst[lane] + abv;
        v0 = v0 >= 0.f ? v0 : 0.3f * v0;
        float e0 = (adjb[i * NN + lane] > 0) ? v0 : -1e30f;
        float e1 = -1e30f;
        if (j2 < NN) {
            float v1 = ai + adst[j2] + abv;
            v1 = v1 >= 0.f ? v1 : 0.3f * v1;
            e1 = (adjb[i * NN + j2] > 0) ? v1 : -1e30f;
        }
        float m = fmaxf(e0, e1);
        #pragma unroll
        for (int o = 16; o; o >>= 1) m = fmaxf(m, __shfl_xor_sync(~0u, m, o));
        float x0 = expf(e0 - m);
        float x1 = (j2 < NN) ? expf(e1 - m) : 0.f;
        float s = x0 + x1;
        #pragma unroll
        for (int o = 16; o; o >>= 1) s += __shfl_xor_sync(~0u, s, o);
        float inv = 1.f / s;
        att[((size_t)b * NN + i) * NN + lane] = x0 * inv;
        if (j2 < NN) att[((size_t)b * NN + i) * NN + j2] = x1 * inv;
    }
}

// ---------------- 4) apply attention: out = elu(att @ Wh) (+ residual) -----
__global__ __launch_bounds__(256) void gat_apply_kernel(
    const float* __restrict__ att, const float* __restrict__ Wh,
    const float* __restrict__ resid, float* __restrict__ out)
{
    int b = blockIdx.y, ch = blockIdx.x;       // 6 chunks of 128 cols
    __shared__ float att_s[NN * NN];           // 10 KB
    __shared__ float whs[NN][128];             // 25.6 KB
    int t = threadIdx.x;
    for (int idx = t; idx < NN * NN; idx += 256)
        att_s[idx] = att[(size_t)b * NN * NN + idx];
    const float* whb = Wh + (size_t)b * NN * HH + ch * 128;
    for (int idx = t; idx < NN * 32; idx += 256) {
        int r = idx >> 5, c = (idx & 31) * 4;
        *(float4*)&whs[r][c] = *(const float4*)(whb + (size_t)r * HH + c);
    }
    __syncthreads();
    int hl = t & 127, i0 = t >> 7;
    for (int i = i0; i < NN; i += 4) {
        int ib = (i + 2 < NN) ? i + 2 : i;     // clamp (masked at store)
        float acc0 = 0.f, acc1 = 0.f;
        #pragma unroll
        for (int j = 0; j < NN; j++) {
            float wv = whs[j][hl];
            acc0 = fmaf(att_s[i * NN + j], wv, acc0);
            acc1 = fmaf(att_s[ib * NN + j], wv, acc1);
        }
        float val0 = acc0 > 0.f ? acc0 : expm1f(acc0);
        size_t off0 = ((size_t)b * NN + i) * HH + ch * 128 + hl;
        if (resid) val0 += resid[off0];
        out[off0] = val0;
        if (ib != i) {
            float val1 = acc1 > 0.f ? acc1 : expm1f(acc1);
            size_t off1 = ((size_t)b * NN + ib) * HH + ch * 128 + hl;
            if (resid) val1 += resid[off1];
            out[off1] = val1;
        }
    }
}

// ---------------- 5) attention pooling over N utterances -------------------
__global__ void pool_kernel(const float* __restrict__ T,
                            const float* __restrict__ v,
                            const float* __restrict__ Hres,
                            float* __restrict__ D)
{
    int b = blockIdx.x;
    int t = threadIdx.x, lane = t & 31, w = t >> 5;
    __shared__ float sc[NN];
    for (int n = w; n < NN; n += 8) {
        const float4* row = (const float4*)(T + ((size_t)b * NN + n) * HH);
        float s = 0.f;
        for (int c2 = lane; c2 < HH / 4; c2 += 32) {
            float4 x = row[c2];
            float4 u = ((const float4*)v)[c2];
            s += tanhf(x.x) * u.x + tanhf(x.y) * u.y +
                 tanhf(x.z) * u.z + tanhf(x.w) * u.w;
        }
        #pragma unroll
        for (int o = 16; o; o >>= 1) s += __shfl_xor_sync(~0u, s, o);
        if (lane == 0) sc[n] = s;
    }
    __syncthreads();
    if (t == 0) {
        float m = -1e30f;
        for (int n = 0; n < NN; n++) m = fmaxf(m, sc[n]);
        float s = 0.f;
        for (int n = 0; n < NN; n++) { sc[n] = expf(sc[n] - m); s += sc[n]; }
        float inv = 1.f / s;
        for (int n = 0; n < NN; n++) sc[n] *= inv;
    }
    __syncthreads();
    for (int h = t; h < HH; h += 256) {
        float acc = 0.f;
        #pragma unroll 5
        for (int n = 0; n < NN; n++)
            acc = fmaf(sc[n], Hres[((size_t)b * NN + n) * HH + h], acc);
        D[(size_t)b * HH + h] = acc;
    }
}

// ---------------- launch ----------------------------------------------------
extern "C" void kernel_launch(void* const* d_in, const int* in_sizes, int n_in,
                              void* d_out, int out_size)
{
    const float* emb = (const float*)d_in[0];
    const int*   ids = (const int*)  d_in[1];
    const int*   adj = (const int*)  d_in[2];
    const float* W1  = (const float*)d_in[3];
    const float* b1  = (const float*)d_in[4];
    const float* a1  = (const float*)d_in[5];
    const float* ab1 = (const float*)d_in[6];
    const float* W2  = (const float*)d_in[7];
    const float* b2  = (const float*)d_in[8];
    const float* a2  = (const float*)d_in[9];
    const float* ab2 = (const float*)d_in[10];
    const float* Wa  = (const float*)d_in[11];
    const float* ba  = (const float*)d_in[12];
    const float* v   = (const float*)d_in[13];
    const float* Wl  = (const float*)d_in[14];
    const float* bl  = (const float*)d_in[15];
    float* out = (float*)d_out;

    void *pX, *pWh, *pH1, *pHres, *pT, *pAtt, *pD, *pAh, *pAl, *pBh, *pBl;
    cudaGetSymbolAddress(&pX, g_X);
    cudaGetSymbolAddress(&pWh, g_Wh);
    cudaGetSymbolAddress(&pH1, g_H1);
    cudaGetSymbolAddress(&pHres, g_Hres);
    cudaGetSymbolAddress(&pT, g_T);
    cudaGetSymbolAddress(&pAtt, g_att);
    cudaGetSymbolAddress(&pD, g_D);
    cudaGetSymbolAddress(&pAh, g_Ah);
    cudaGetSymbolAddress(&pAl, g_Al);
    cudaGetSymbolAddress(&pBh, g_Bh);
    cudaGetSymbolAddress(&pBl, g_Bl);
    float* X    = (float*)pX;
    float* Wh   = (float*)pWh;
    float* H1   = (float*)pH1;
    float* Hres = (float*)pHres;
    float* T    = (float*)pT;
    float* Att  = (float*)pAtt;
    float* D    = (float*)pD;
    __nv_bfloat16* Ah = (__nv_bfloat16*)pAh;
    __nv_bfloat16* Al = (__nv_bfloat16*)pAl;
    __nv_bfloat16* Bh = (__nv_bfloat16*)pBh;
    __nv_bfloat16* Bl = (__nv_bfloat16*)pBl;

    cudaFuncSetAttribute(gemm_bf16x3,
                         cudaFuncAttributeMaxDynamicSharedMemorySize,
                         SMEM_BF16 * 2);

    const int n4A = MTOT * HH / 4;   // 614400
    const int n4W = HH * HH / 4;     // 147456
    const int n4D = BB * HH / 4;     // 12288
    dim3 ggemm(HH / 128, MTOT / 128);   // (6, 25)
    dim3 gfin(HH / 128, 1);
    dim3 gapply(HH / 128, BB);
    const size_t smem = SMEM_BF16 * 2;

    // 1) gather + PE
    gather_pe_kernel<<<MTOT, HH / 4>>>(emb, ids);

    // 2) Wh1 = X @ W1 + b1   (tensor path)
    split_bf16_kernel<<<(n4A + 255) / 256, 256>>>(X, Ah, Al, n4A);
    split_bf16_kernel<<<(n4W + 255) / 256, 256>>>(W1, Bh, Bl, n4W);
    gemm_bf16x3<<<ggemm, 256, smem>>>(Ah, Al, Bh, Bl, b1, Wh, MTOT);

    // 3) GAT layer 1 attention + apply (elu)
    gat_att_kernel<<<BB, 256>>>(Wh, a1, ab1, adj, Att);
    gat_apply_kernel<<<gapply, 256>>>(Att, Wh, nullptr, H1);

    // 4) Wh2 = H1 @ W2 + b2
    split_bf16_kernel<<<(n4A + 255) / 256, 256>>>(H1, Ah, Al, n4A);
    split_bf16_kernel<<<(n4W + 255) / 256, 256>>>(W2, Bh, Bl, n4W);
    gemm_bf16x3<<<ggemm, 256, smem>>>(Ah, Al, Bh, Bl, b2, Wh, MTOT);

    // 5) GAT layer 2 attention + apply (elu + residual X)
    gat_att_kernel<<<BB, 256>>>(Wh, a2, ab2, adj, Att);
    gat_apply_kernel<<<gapply, 256>>>(Att, Wh, X, Hres);

    // 6) T = Hres @ Wa + ba
    split_bf16_kernel<<<(n4A + 255) / 256, 256>>>(Hres, Ah, Al, n4A);
    split_bf16_kernel<<<(n4W + 255) / 256, 256>>>(Wa, Bh, Bl, n4W);
    gemm_bf16x3<<<ggemm, 256, smem>>>(Ah, Al, Bh, Bl, ba, T, MTOT);

    // 7) attention pooling -> D[64,768]
    pool_kernel<<<BB, 256>>>(T, v, Hres, D);

    // 8) out = D @ Wl + bl (tensor path, M=64 guarded)
    split_bf16_kernel<<<(n4D + 255) / 256, 256>>>(D, Ah, Al, n4D);
    split_bf16_kernel<<<(n4W + 255) / 256, 256>>>(Wl, Bh, Bl, n4W);
    gemm_bf16x3<<<gfin, 256, smem>>>(Ah, Al, Bh, Bl, bl, out, BB);
}

// round 5
// speedup vs baseline: 2.0992x; 1.0342x over previous
#include <cuda_runtime.h>
#include <cuda_bf16.h>
#include <math.h>

#define BB 64
#define LL 512
#define HH 768
#define NN 50
#define OO 768
#define MTOT (BB*NN)   // 3200

// ---------------- scratch (device globals; no allocations allowed) ----------
__device__ float g_X[MTOT*HH];     // gathered + positional-encoded input (fp32, residual)
__device__ float g_Wh[MTOT*HH];    // Wh of current GAT layer
__device__ float g_Hres[MTOT*HH];  // elu(gat2) + X (fp32, needed by pool)
__device__ float g_T[MTOT*HH];     // Hres@Wa + ba
__device__ float g_att[BB*NN*NN];  // attention matrices
// bf16 split buffers
__device__ __nv_bfloat16 g_Ah[MTOT*HH];
__device__ __nv_bfloat16 g_Al[MTOT*HH];
__device__ __nv_bfloat16 g_Bh[4*HH*HH];   // W1,W2,Wa,Wl hi
__device__ __nv_bfloat16 g_Bl[4*HH*HH];   // W1,W2,Wa,Wl lo

__device__ __forceinline__ void split1(float v, __nv_bfloat16& h, __nv_bfloat16& l) {
    h = __float2bfloat16(v);
    l = __float2bfloat16(v - __bfloat162float(h));
}

// ---------------- 0) split the 4 weight matrices (one launch) --------------
__global__ void split_weights_kernel(const float* __restrict__ w0,
                                     const float* __restrict__ w1,
                                     const float* __restrict__ w2,
                                     const float* __restrict__ w3)
{
    const float* srcs[4] = {w0, w1, w2, w3};
    int m = blockIdx.y;
    int i = blockIdx.x * blockDim.x + threadIdx.x;   // float4 index
    const int n4 = HH * HH / 4;
    if (i >= n4) return;
    float4 v = ((const float4*)srcs[m])[i];
    __nv_bfloat16 h0,h1,h2,h3,l0,l1,l2,l3;
    split1(v.x,h0,l0); split1(v.y,h1,l1); split1(v.z,h2,l2); split1(v.w,h3,l3);
    __nv_bfloat162* H = (__nv_bfloat162*)(g_Bh + (size_t)m * HH * HH);
    __nv_bfloat162* L = (__nv_bfloat162*)(g_Bl + (size_t)m * HH * HH);
    H[2*i]   = __nv_bfloat162(h0,h1);
    H[2*i+1] = __nv_bfloat162(h2,h3);
    L[2*i]   = __nv_bfloat162(l0,l1);
    L[2*i+1] = __nv_bfloat162(l2,l3);
}

// ---------------- 1) gather + sinusoidal PE (+ bf16 split of X) ------------
__global__ void gather_pe_kernel(const float* __restrict__ emb,
                                 const int* __restrict__ ids)
{
    int bn = blockIdx.x;            // 0..3199
    int b = bn / NN, n = bn % NN;
    int h = threadIdx.x * 4;        // 192 threads * 4 = 768
    int id = ids[bn];
    float4 e = *(const float4*)(emb + ((size_t)b * LL + id) * HH + h);
    const float c = -logf(10000.0f) / (float)HH;
    float d0 = expf((float)h * c);
    float d1 = expf((float)(h + 2) * c);
    float a0 = (float)n * d0, a1 = (float)n * d1;
    e.x += sinf(a0); e.y += cosf(a0);
    e.z += sinf(a1); e.w += cosf(a1);
    size_t off = (size_t)bn * HH + h;
    *(float4*)(g_X + off) = e;
    __nv_bfloat16 h0,h1,h2,h3,l0,l1,l2,l3;
    split1(e.x,h0,l0); split1(e.y,h1,l1); split1(e.z,h2,l2); split1(e.w,h3,l3);
    *(__nv_bfloat162*)(g_Ah + off)     = __nv_bfloat162(h0,h1);
    *(__nv_bfloat162*)(g_Ah + off + 2) = __nv_bfloat162(h2,h3);
    *(__nv_bfloat162*)(g_Al + off)     = __nv_bfloat162(l0,l1);
    *(__nv_bfloat162*)(g_Al + off + 2) = __nv_bfloat162(l2,l3);
}

// ---------------- tensor-core GEMM (bf16x3 split, fp32 accum) --------------
// C[M,768] = A[M,768] @ W[768,768] + bias.  3-stage cp.async ring, 1 sync/chunk.
#define STG 3
#define SA_ELEMS (2*128*40)                 // 10240
#define SB_ELEMS (2*32*136)                 // 8704
#define STAGE_ELEMS (SA_ELEMS + SB_ELEMS)   // 18944
#define SA_IDX(st,sp,r,c) ((size_t)(st)*STAGE_ELEMS + ((sp)*128 + (r))*40 + (c))
#define SB_IDX(st,sp,r,c) ((size_t)(st)*STAGE_ELEMS + SA_ELEMS + ((sp)*32 + (r))*136 + (c))
#define SMEM_BYTES (STG * STAGE_ELEMS * 2)  // 113664 B

#define CP16(dst, src) \
    asm volatile("cp.async.cg.shared.global [%0], [%1], 16;\n" :: "r"(dst), "l"(src))

__device__ __forceinline__ void ldsm4(unsigned* r, const void* p) {
    unsigned addr = (unsigned)__cvta_generic_to_shared(p);
    asm volatile("ldmatrix.sync.aligned.m8n8.x4.shared.b16 {%0,%1,%2,%3}, [%4];\n"
                 : "=r"(r[0]), "=r"(r[1]), "=r"(r[2]), "=r"(r[3]) : "r"(addr));
}
__device__ __forceinline__ void ldsm4t(unsigned* r, const void* p) {
    unsigned addr = (unsigned)__cvta_generic_to_shared(p);
    asm volatile("ldmatrix.sync.aligned.m8n8.x4.trans.shared.b16 {%0,%1,%2,%3}, [%4];\n"
                 : "=r"(r[0]), "=r"(r[1]), "=r"(r[2]), "=r"(r[3]) : "r"(addr));
}
__device__ __forceinline__ void mma16816(float* c, const unsigned* a, const unsigned* b) {
    asm volatile("mma.sync.aligned.m16n8k16.row.col.f32.bf16.bf16.f32 "
                 "{%0,%1,%2,%3}, {%4,%5,%6,%7}, {%8,%9}, {%0,%1,%2,%3};\n"
                 : "+f"(c[0]), "+f"(c[1]), "+f"(c[2]), "+f"(c[3])
                 : "r"(a[0]), "r"(a[1]), "r"(a[2]), "r"(a[3]),
                   "r"(b[0]), "r"(b[1]));
}

__global__ __launch_bounds__(256, 1) void gemm_bf16x3(
    const __nv_bfloat16* __restrict__ Ah, const __nv_bfloat16* __restrict__ Al,
    const __nv_bfloat16* __restrict__ Bh, const __nv_bfloat16* __restrict__ Bl,
    const float* __restrict__ bias, float* __restrict__ C, int M)
{
    extern __shared__ __nv_bfloat16 sm[];
    const int tid = threadIdx.x;
    const int lane = tid & 31, wid = tid >> 5;
    const int warp_m = wid >> 1, warp_n = wid & 1;
    const int bm = blockIdx.y * 128, bn = blockIdx.x * 128;

    const int ar = tid >> 2, ac = (tid & 3) * 8;    // A: 64 rows/pass
    const int br = tid >> 4, bc = (tid & 15) * 8;   // B: 16 rows/pass
    const int rA0 = min(bm + ar, M - 1);            // clamp (masked at store)
    const int rA1 = min(bm + ar + 64, M - 1);

    float acc[2][8][4] = {};
    const __nv_bfloat16* As[2] = {Ah, Al};
    const __nv_bfloat16* Bs[2] = {Bh, Bl};

    auto load_stage = [&](int st, int k0) {
        #pragma unroll
        for (int s = 0; s < 2; s++) {
            unsigned d0 = (unsigned)__cvta_generic_to_shared(&sm[SA_IDX(st, s, ar, ac)]);
            CP16(d0, As[s] + (size_t)rA0 * HH + k0 + ac);
            unsigned d1 = (unsigned)__cvta_generic_to_shared(&sm[SA_IDX(st, s, ar + 64, ac)]);
            CP16(d1, As[s] + (size_t)rA1 * HH + k0 + ac);
            unsigned e0 = (unsigned)__cvta_generic_to_shared(&sm[SB_IDX(st, s, br, bc)]);
            CP16(e0, Bs[s] + (size_t)(k0 + br) * HH + bn + bc);
            unsigned e1 = (unsigned)__cvta_generic_to_shared(&sm[SB_IDX(st, s, br + 16, bc)]);
            CP16(e1, Bs[s] + (size_t)(k0 + br + 16) * HH + bn + bc);
        }
        asm volatile("cp.async.commit_group;\n" ::: "memory");
    };

    // prologue: stages 0,1 in flight
    load_stage(0, 0);
    load_stage(1, 32);

    const int lrow = lane & 15, lcol = (lane >> 4) * 8;
    const int NCH = HH / 32;   // 24

    for (int c = 0; c < NCH; c++) {
        // complete the group for stage c
        if (c < NCH - 1) asm volatile("cp.async.wait_group 1;\n" ::: "memory");
        else             asm volatile("cp.async.wait_group 0;\n" ::: "memory");
        __syncthreads();                    // data visible + prev-stage slot free
        if (c + 2 < NCH) load_stage((c + 2) % STG, (c + 2) * 32);   // overlap with compute
        const int st = c % STG;

        #pragma unroll
        for (int ks = 0; ks < 2; ks++) {
            const int kb = ks * 16;
            unsigned a[2][2][4];   // [split][mtile][4]
            #pragma unroll
            for (int mt = 0; mt < 2; mt++)
                #pragma unroll
                for (int s = 0; s < 2; s++)
                    ldsm4(a[s][mt], &sm[SA_IDX(st, s, warp_m * 32 + mt * 16 + lrow, kb + lcol)]);
            unsigned b[2][8][2];   // [split][ntile][2]
            #pragma unroll
            for (int g = 0; g < 4; g++)
                #pragma unroll
                for (int s = 0; s < 2; s++) {
                    unsigned r[4];
                    ldsm4t(r, &sm[SB_IDX(st, s, kb + lrow, warp_n * 64 + g * 16 + lcol)]);
                    b[s][2*g][0]   = r[0]; b[s][2*g][1]   = r[1];
                    b[s][2*g+1][0] = r[2]; b[s][2*g+1][1] = r[3];
                }
            #pragma unroll
            for (int mt = 0; mt < 2; mt++)
                #pragma unroll
                for (int nt = 0; nt < 8; nt++) {
                    mma16816(acc[mt][nt], a[0][mt], b[0][nt]);   // hi*hi
                    mma16816(acc[mt][nt], a[0][mt], b[1][nt]);   // hi*lo
                    mma16816(acc[mt][nt], a[1][mt], b[0][nt]);   // lo*hi
                }
        }
        __syncthreads();   // all warps done with stage st before it is overwritten
    }

    // ---- epilogue: bias add, fp32 store ----
    const int er = bm + warp_m * 32 + (lane >> 2);
    const int ec = bn + warp_n * 64 + (lane & 3) * 2;
    #pragma unroll
    for (int mt = 0; mt < 2; mt++)
        #pragma unroll
        for (int nt = 0; nt < 8; nt++) {
            int r = er + mt * 16;
            int cc = ec + nt * 8;
            float b0 = bias[cc], b1 = bias[cc + 1];
            if (r < M) {
                C[(size_t)r * HH + cc]     = acc[mt][nt][0] + b0;
                C[(size_t)r * HH + cc + 1] = acc[mt][nt][1] + b1;
            }
            if (r + 8 < M) {
                C[(size_t)(r + 8) * HH + cc]     = acc[mt][nt][2] + b0;
                C[(size_t)(r + 8) * HH + cc + 1] = acc[mt][nt][3] + b1;
            }
        }
}

// ---------------- 3) GAT attention: masked softmax of leaky_relu scores ----
__global__ void gat_att_kernel(const float* __restrict__ Wh,
                               const float* __restrict__ a,
                               const float* __restrict__ ab,
                               const int* __restrict__ adj,
                               float* __restrict__ att)
{
    int b = blockIdx.x;
    int t = threadIdx.x, lane = t & 31, w = t >> 5;   // 8 warps
    __shared__ float asrc[NN], adst[NN];
    const float* whb = Wh + (size_t)b * NN * HH;

    for (int n = w; n < NN; n += 8) {
        const float4* row = (const float4*)(whb + (size_t)n * HH);
        float s1 = 0.f, s2 = 0.f;
        for (int c2 = lane; c2 < HH / 4; c2 += 32) {
            float4 x = row[c2];
            float4 u = ((const float4*)a)[c2];
            float4 v = ((const float4*)a)[HH / 4 + c2];
            s1 += x.x * u.x + x.y * u.y + x.z * u.z + x.w * u.w;
            s2 += x.x * v.x + x.y * v.y + x.z * v.z + x.w * v.w;
        }
        #pragma unroll
        for (int o = 16; o; o >>= 1) {
            s1 += __shfl_xor_sync(~0u, s1, o);
            s2 += __shfl_xor_sync(~0u, s2, o);
        }
        if (lane == 0) { asrc[n] = s1; adst[n] = s2; }
    }
    __syncthreads();

    float abv = *ab;
    const int* adjb = adj + b * NN * NN;
    for (int i = w; i < NN; i += 8) {
        float ai = asrc[i];
        int j2 = lane + 32;
        float v0 = ai + adst[lane] + abv;
        v0 = v0 >= 0.f ? v0 : 0.3f * v0;
        float e0 = (adjb[i * NN + lane] > 0) ? v0 : -1e30f;
        float e1 = -1e30f;
        if (j2 < NN) {
            float v1 = ai + adst[j2] + abv;
            v1 = v1 >= 0.f ? v1 : 0.3f * v1;
            e1 = (adjb[i * NN + j2] > 0) ? v1 : -1e30f;
        }
        float m = fmaxf(e0, e1);
        #pragma unroll
        for (int o = 16; o; o >>= 1) m = fmaxf(m, __shfl_xor_sync(~0u, m, o));
        float x0 = expf(e0 - m);
        float x1 = (j2 < NN) ? expf(e1 - m) : 0.f;
        float s = x0 + x1;
        #pragma unroll
        for (int o = 16; o; o >>= 1) s += __shfl_xor_sync(~0u, s, o);
        float inv = 1.f / s;
        att[((size_t)b * NN + i) * NN + lane] = x0 * inv;
        if (j2 < NN) att[((size_t)b * NN + i) * NN + j2] = x1 * inv;
    }
}

// ------- 4) apply attention: val = elu(att@Wh) (+resid); writes bf16 split --
// out_f32 may be null (fp32 copy skipped); hi/lo always written (GEMM input)
__global__ __launch_bounds__(256) void gat_apply_kernel(
    const float* __restrict__ att, const float* __restrict__ Wh,
    const float* __restrict__ resid, float* __restrict__ out_f32,
    __nv_bfloat16* __restrict__ hi, __nv_bfloat16* __restrict__ lo)
{
    int b = blockIdx.y, ch = blockIdx.x;       // 6 chunks of 128 cols
    __shared__ float att_s[NN * NN];           // 10 KB
    __shared__ float whs[NN][128];             // 25.6 KB
    int t = threadIdx.x;
    for (int idx = t; idx < NN * NN; idx += 256)
        att_s[idx] = att[(size_t)b * NN * NN + idx];
    const float* whb = Wh + (size_t)b * NN * HH + ch * 128;
    for (int idx = t; idx < NN * 32; idx += 256) {
        int r = idx >> 5, c = (idx & 31) * 4;
        *(float4*)&whs[r][c] = *(const float4*)(whb + (size_t)r * HH + c);
    }
    __syncthreads();
    int hl = t & 127, i0 = t >> 7;
    for (int i = i0; i < NN; i += 4) {
        int ib = (i + 2 < NN) ? i + 2 : i;     // clamp (dup row, store guarded)
        float acc0 = 0.f, acc1 = 0.f;
        #pragma unroll
        for (int j = 0; j < NN; j++) {
            float wv = whs[j][hl];
            acc0 = fmaf(att_s[i * NN + j], wv, acc0);
            acc1 = fmaf(att_s[ib * NN + j], wv, acc1);
        }
        float val0 = acc0 > 0.f ? acc0 : expm1f(acc0);
        size_t off0 = ((size_t)b * NN + i) * HH + ch * 128 + hl;
        if (resid) val0 += resid[off0];
        if (out_f32) out_f32[off0] = val0;
        split1(val0, hi[off0], lo[off0]);
        if (ib != i) {
            float val1 = acc1 > 0.f ? acc1 : expm1f(acc1);
            size_t off1 = ((size_t)b * NN + ib) * HH + ch * 128 + hl;
            if (resid) val1 += resid[off1];
            if (out_f32) out_f32[off1] = val1;
            split1(val1, hi[off1], lo[off1]);
        }
    }
}

// -------- 5) attention pooling; writes bf16 split of D directly ------------
__global__ void pool_kernel(const float* __restrict__ T,
                            const float* __restrict__ v,
                            const float* __restrict__ Hres,
                            __nv_bfloat16* __restrict__ Dh,
                            __nv_bfloat16* __restrict__ Dl)
{
    int b = blockIdx.x;
    int t = threadIdx.x, lane = t & 31, w = t >> 5;
    __shared__ float sc[NN];
    for (int n = w; n < NN; n += 8) {
        const float4* row = (const float4*)(T + ((size_t)b * NN + n) * HH);
        float s = 0.f;
        for (int c2 = lane; c2 < HH / 4; c2 += 32) {
            float4 x = row[c2];
            float4 u = ((const float4*)v)[c2];
            s += tanhf(x.x) * u.x + tanhf(x.y) * u.y +
                 tanhf(x.z) * u.z + tanhf(x.w) * u.w;
        }
        #pragma unroll
        for (int o = 16; o; o >>= 1) s += __shfl_xor_sync(~0u, s, o);
        if (lane == 0) sc[n] = s;
    }
    __syncthreads();
    if (t == 0) {
        float m = -1e30f;
        for (int n = 0; n < NN; n++) m = fmaxf(m, sc[n]);
        float s = 0.f;
        for (int n = 0; n < NN; n++) { sc[n] = expf(sc[n] - m); s += sc[n]; }
        float inv = 1.f / s;
        for (int n = 0; n < NN; n++) sc[n] *= inv;
    }
    __syncthreads();
    for (int h = t; h < HH; h += 256) {
        float acc = 0.f;
        #pragma unroll 5
        for (int n = 0; n < NN; n++)
            acc = fmaf(sc[n], Hres[((size_t)b * NN + n) * HH + h], acc);
        size_t off = (size_t)b * HH + h;
        split1(acc, Dh[off], Dl[off]);
    }
}

// ---------------- launch ----------------------------------------------------
extern "C" void kernel_launch(void* const* d_in, const int* in_sizes, int n_in,
                              void* d_out, int out_size)
{
    const float* emb = (const float*)d_in[0];
    const int*   ids = (const int*)  d_in[1];
    const int*   adj = (const int*)  d_in[2];
    const float* W1  = (const float*)d_in[3];
    const float* b1  = (const float*)d_in[4];
    const float* a1  = (const float*)d_in[5];
    const float* ab1 = (const float*)d_in[6];
    const float* W2  = (const float*)d_in[7];
    const float* b2  = (const float*)d_in[8];
    const float* a2  = (const float*)d_in[9];
    const float* ab2 = (const float*)d_in[10];
    const float* Wa  = (const float*)d_in[11];
    const float* ba  = (const float*)d_in[12];
    const float* v   = (const float*)d_in[13];
    const float* Wl  = (const float*)d_in[14];
    const float* bl  = (const float*)d_in[15];
    float* out = (float*)d_out;

    void *pX, *pWh, *pHres, *pT, *pAtt, *pAh, *pAl, *pBh, *pBl;
    cudaGetSymbolAddress(&pX, g_X);
    cudaGetSymbolAddress(&pWh, g_Wh);
    cudaGetSymbolAddress(&pHres, g_Hres);
    cudaGetSymbolAddress(&pT, g_T);
    cudaGetSymbolAddress(&pAtt, g_att);
    cudaGetSymbolAddress(&pAh, g_Ah);
    cudaGetSymbolAddress(&pAl, g_Al);
    cudaGetSymbolAddress(&pBh, g_Bh);
    cudaGetSymbolAddress(&pBl, g_Bl);
    float* X    = (float*)pX;
    float* Wh   = (float*)pWh;
    float* Hres = (float*)pHres;
    float* T    = (float*)pT;
    float* Att  = (float*)pAtt;
    __nv_bfloat16* Ah = (__nv_bfloat16*)pAh;
    __nv_bfloat16* Al = (__nv_bfloat16*)pAl;
    __nv_bfloat16* Bh = (__nv_bfloat16*)pBh;
    __nv_bfloat16* Bl = (__nv_bfloat16*)pBl;
    const size_t WSZ = (size_t)HH * HH;

    cudaFuncSetAttribute(gemm_bf16x3,
                         cudaFuncAttributeMaxDynamicSharedMemorySize, SMEM_BYTES);

    dim3 ggemm(HH / 128, MTOT / 128);   // (6, 25)
    dim3 gfin(HH / 128, 1);
    dim3 gapply(HH / 128, BB);
    dim3 gsplitw((HH * HH / 4 + 255) / 256, 4);

    // 0) weights -> bf16 splits (all four at once)
    split_weights_kernel<<<gsplitw, 256>>>(W1, W2, Wa, Wl);
    // 1) gather + PE (+ split of X)
    gather_pe_kernel<<<MTOT, HH / 4>>>(emb, ids);
    // 2) Wh1 = X @ W1 + b1
    gemm_bf16x3<<<ggemm, 256, SMEM_BYTES>>>(Ah, Al, Bh, Bl, b1, Wh, MTOT);
    // 3) GAT layer 1: attention + apply (elu) -> split(H1) only
    gat_att_kernel<<<BB, 256>>>(Wh, a1, ab1, adj, Att);
    gat_apply_kernel<<<gapply, 256>>>(Att, Wh, nullptr, nullptr, Ah, Al);
    // 4) Wh2 = H1 @ W2 + b2
    gemm_bf16x3<<<ggemm, 256, SMEM_BYTES>>>(Ah, Al, Bh + WSZ, Bl + WSZ, b2, Wh, MTOT);
    // 5) GAT layer 2: attention + apply (elu + residual X) -> Hres fp32 + split
    gat_att_kernel<<<BB, 256>>>(Wh, a2, ab2, adj, Att);
    gat_apply_kernel<<<gapply, 256>>>(Att, Wh, X, Hres, Ah, Al);
    // 6) T = Hres @ Wa + ba
    gemm_bf16x3<<<ggemm, 256, SMEM_BYTES>>>(Ah, Al, Bh + 2*WSZ, Bl + 2*WSZ, ba, T, MTOT);
    // 7) attention pooling -> split(D) into Ah/Al rows 0..63
    pool_kernel<<<BB, 256>>>(T, v, Hres, Ah, Al);
    // 8) out = D @ Wl + bl
    gemm_bf16x3<<<gfin, 256, SMEM_BYTES>>>(Ah, Al, Bh + 3*WSZ, Bl + 3*WSZ, bl, out, BB);
}

// round 6
// speedup vs baseline: 2.2312x; 1.0629x over previous
#include <cuda_runtime.h>
#include <cuda_bf16.h>
#include <math.h>

#define BB 64
#define LL 512
#define HH 768
#define NN 50
#define OO 768
#define MTOT (BB*NN)   // 3200

// ---------------- scratch (device globals; no allocations allowed) ----------
__device__ float g_X[MTOT*HH];     // gathered + positional-encoded input (fp32, residual)
__device__ float g_Wh[MTOT*HH];    // Wh of current GAT layer
__device__ float g_Hres[MTOT*HH];  // elu(gat2) + X (fp32, needed by pool)
__device__ float g_T[MTOT*HH];     // Hres@Wa + ba
__device__ float g_att[BB*NN*NN];  // attention matrices
__device__ float g_asrc[MTOT];     // per-row src scores
__device__ float g_adst[MTOT];     // per-row dst scores
__device__ float g_D[BB*HH];       // pooled dialogue vectors (fp32)
// bf16 split buffers
__device__ __nv_bfloat16 g_Ah[MTOT*HH];
__device__ __nv_bfloat16 g_Al[MTOT*HH];
__device__ __nv_bfloat16 g_Bh[3*HH*HH];   // W1,W2,Wa hi
__device__ __nv_bfloat16 g_Bl[3*HH*HH];   // W1,W2,Wa lo

__device__ __forceinline__ void split1(float v, __nv_bfloat16& h, __nv_bfloat16& l) {
    h = __float2bfloat16(v);
    l = __float2bfloat16(v - __bfloat162float(h));
}

// ---------------- 0) split the 3 mma weight matrices (one launch) ----------
__global__ void split_weights_kernel(const float* __restrict__ w0,
                                     const float* __restrict__ w1,
                                     const float* __restrict__ w2)
{
    const float* srcs[3] = {w0, w1, w2};
    int m = blockIdx.y;
    int i = blockIdx.x * blockDim.x + threadIdx.x;   // float4 index
    const int n4 = HH * HH / 4;
    if (i >= n4) return;
    float4 v = ((const float4*)srcs[m])[i];
    __nv_bfloat16 h0,h1,h2,h3,l0,l1,l2,l3;
    split1(v.x,h0,l0); split1(v.y,h1,l1); split1(v.z,h2,l2); split1(v.w,h3,l3);
    __nv_bfloat162* H = (__nv_bfloat162*)(g_Bh + (size_t)m * HH * HH);
    __nv_bfloat162* L = (__nv_bfloat162*)(g_Bl + (size_t)m * HH * HH);
    H[2*i]   = __nv_bfloat162(h0,h1);
    H[2*i+1] = __nv_bfloat162(h2,h3);
    L[2*i]   = __nv_bfloat162(l0,l1);
    L[2*i+1] = __nv_bfloat162(l2,l3);
}

// ---------------- 1) gather + sinusoidal PE (+ bf16 split of X) ------------
__global__ void gather_pe_kernel(const float* __restrict__ emb,
                                 const int* __restrict__ ids)
{
    int bn = blockIdx.x;            // 0..3199
    int b = bn / NN, n = bn % NN;
    int h = threadIdx.x * 4;        // 192 threads * 4 = 768
    int id = ids[bn];
    float4 e = *(const float4*)(emb + ((size_t)b * LL + id) * HH + h);
    const float c = -logf(10000.0f) / (float)HH;
    float d0 = expf((float)h * c);
    float d1 = expf((float)(h + 2) * c);
    float a0 = (float)n * d0, a1 = (float)n * d1;
    e.x += sinf(a0); e.y += cosf(a0);
    e.z += sinf(a1); e.w += cosf(a1);
    size_t off = (size_t)bn * HH + h;
    *(float4*)(g_X + off) = e;
    __nv_bfloat16 h0,h1,h2,h3,l0,l1,l2,l3;
    split1(e.x,h0,l0); split1(e.y,h1,l1); split1(e.z,h2,l2); split1(e.w,h3,l3);
    *(__nv_bfloat162*)(g_Ah + off)     = __nv_bfloat162(h0,h1);
    *(__nv_bfloat162*)(g_Ah + off + 2) = __nv_bfloat162(h2,h3);
    *(__nv_bfloat162*)(g_Al + off)     = __nv_bfloat162(l0,l1);
    *(__nv_bfloat162*)(g_Al + off + 2) = __nv_bfloat162(l2,l3);
}

// ---------------- tensor-core GEMM (bf16x3 split, fp32 accum) --------------
// C[M,768] = A[M,768] @ W[768,768] + bias.  K-chunk 64, 2-stage cp.async.
#define KC 64
#define SA_ELEMS (2*128*72)                 // 18432
#define SB_ELEMS (2*64*136)                 // 17408
#define STAGE_ELEMS (SA_ELEMS + SB_ELEMS)   // 35840
#define SA_IDX(st,sp,r,c) ((size_t)(st)*STAGE_ELEMS + ((sp)*128 + (r))*72 + (c))
#define SB_IDX(st,sp,r,c) ((size_t)(st)*STAGE_ELEMS + SA_ELEMS + ((sp)*64 + (r))*136 + (c))
#define SMEM_BYTES (2 * STAGE_ELEMS * 2)    // 143360 B

#define CP16(dst, src) \
    asm volatile("cp.async.cg.shared.global [%0], [%1], 16;\n" :: "r"(dst), "l"(src))

__device__ __forceinline__ void ldsm4(unsigned* r, const void* p) {
    unsigned addr = (unsigned)__cvta_generic_to_shared(p);
    asm volatile("ldmatrix.sync.aligned.m8n8.x4.shared.b16 {%0,%1,%2,%3}, [%4];\n"
                 : "=r"(r[0]), "=r"(r[1]), "=r"(r[2]), "=r"(r[3]) : "r"(addr));
}
__device__ __forceinline__ void ldsm4t(unsigned* r, const void* p) {
    unsigned addr = (unsigned)__cvta_generic_to_shared(p);
    asm volatile("ldmatrix.sync.aligned.m8n8.x4.trans.shared.b16 {%0,%1,%2,%3}, [%4];\n"
                 : "=r"(r[0]), "=r"(r[1]), "=r"(r[2]), "=r"(r[3]) : "r"(addr));
}
__device__ __forceinline__ void mma16816(float* c, const unsigned* a, const unsigned* b) {
    asm volatile("mma.sync.aligned.m16n8k16.row.col.f32.bf16.bf16.f32 "
                 "{%0,%1,%2,%3}, {%4,%5,%6,%7}, {%8,%9}, {%0,%1,%2,%3};\n"
                 : "+f"(c[0]), "+f"(c[1]), "+f"(c[2]), "+f"(c[3])
                 : "r"(a[0]), "r"(a[1]), "r"(a[2]), "r"(a[3]),
                   "r"(b[0]), "r"(b[1]));
}

__global__ __launch_bounds__(256, 1) void gemm_bf16x3(
    const __nv_bfloat16* __restrict__ Ah, const __nv_bfloat16* __restrict__ Al,
    const __nv_bfloat16* __restrict__ Bh, const __nv_bfloat16* __restrict__ Bl,
    const float* __restrict__ bias, float* __restrict__ C, int M)
{
    extern __shared__ __nv_bfloat16 sm[];
    const int tid = threadIdx.x;
    const int lane = tid & 31, wid = tid >> 5;
    const int warp_m = wid >> 1, warp_n = wid & 1;
    const int bm = blockIdx.y * 128, bn = blockIdx.x * 128;

    const int arA = tid >> 1, acA = (tid & 1) * 8;   // A: 128 rows, 4 col passes
    const int brB = tid >> 4, bcB = (tid & 15) * 8;  // B: 16 rows/pass, 4 passes
    const int rA = min(bm + arA, M - 1);             // clamp (masked at store)

    float acc[2][8][4] = {};
    const __nv_bfloat16* As[2] = {Ah, Al};
    const __nv_bfloat16* Bs[2] = {Bh, Bl};

    auto load_stage = [&](int st, int k0) {
        #pragma unroll
        for (int s = 0; s < 2; s++) {
            const __nv_bfloat16* ag = As[s] + (size_t)rA * HH + k0;
            #pragma unroll
            for (int p = 0; p < 4; p++) {
                int col = acA + p * 16;
                unsigned d = (unsigned)__cvta_generic_to_shared(&sm[SA_IDX(st, s, arA, col)]);
                CP16(d, ag + col);
            }
            #pragma unroll
            for (int p = 0; p < 4; p++) {
                int row = brB + p * 16;
                unsigned e = (unsigned)__cvta_generic_to_shared(&sm[SB_IDX(st, s, row, bcB)]);
                CP16(e, Bs[s] + (size_t)(k0 + row) * HH + bn + bcB);
            }
        }
        asm volatile("cp.async.commit_group;\n" ::: "memory");
    };

    load_stage(0, 0);

    const int lrow = lane & 15, lcol = (lane >> 4) * 8;
    const int NCH = HH / KC;   // 12

    for (int c = 0; c < NCH; c++) {
        asm volatile("cp.async.wait_group 0;\n" ::: "memory");
        __syncthreads();                 // stage c visible; compute of c-1 done by all
        if (c + 1 < NCH) load_stage((c + 1) & 1, (c + 1) * KC);   // overlaps compute c
        const int st = c & 1;

        #pragma unroll
        for (int ks = 0; ks < 4; ks++) {
            const int kb = ks * 16;
            unsigned a[2][2][4];   // [split][mtile][4]
            #pragma unroll
            for (int mt = 0; mt < 2; mt++)
                #pragma unroll
                for (int s = 0; s < 2; s++)
                    ldsm4(a[s][mt], &sm[SA_IDX(st, s, warp_m * 32 + mt * 16 + lrow, kb + lcol)]);
            unsigned b[2][8][2];   // [split][ntile][2]
            #pragma unroll
            for (int g = 0; g < 4; g++)
                #pragma unroll
                for (int s = 0; s < 2; s++) {
                    unsigned r[4];
                    ldsm4t(r, &sm[SB_IDX(st, s, kb + lrow, warp_n * 64 + g * 16 + lcol)]);
                    b[s][2*g][0]   = r[0]; b[s][2*g][1]   = r[1];
                    b[s][2*g+1][0] = r[2]; b[s][2*g+1][1] = r[3];
                }
            #pragma unroll
            for (int mt = 0; mt < 2; mt++)
                #pragma unroll
                for (int nt = 0; nt < 8; nt++) {
                    mma16816(acc[mt][nt], a[0][mt], b[0][nt]);   // hi*hi
                    mma16816(acc[mt][nt], a[0][mt], b[1][nt]);   // hi*lo
                    mma16816(acc[mt][nt], a[1][mt], b[0][nt]);   // lo*hi
                }
        }
    }

    // ---- epilogue: bias add, fp32 store ----
    const int er = bm + warp_m * 32 + (lane >> 2);
    const int ec = bn + warp_n * 64 + (lane & 3) * 2;
    #pragma unroll
    for (int mt = 0; mt < 2; mt++)
        #pragma unroll
        for (int nt = 0; nt < 8; nt++) {
            int r = er + mt * 16;
            int cc = ec + nt * 8;
            float b0 = bias[cc], b1 = bias[cc + 1];
            if (r < M) {
                C[(size_t)r * HH + cc]     = acc[mt][nt][0] + b0;
                C[(size_t)r * HH + cc + 1] = acc[mt][nt][1] + b1;
            }
            if (r + 8 < M) {
                C[(size_t)(r + 8) * HH + cc]     = acc[mt][nt][2] + b0;
                C[(size_t)(r + 8) * HH + cc + 1] = acc[mt][nt][3] + b1;
            }
        }
}

// ---------------- 3a) per-row GAT scores: one warp per row -----------------
__global__ void scores_kernel(const float* __restrict__ Wh,
                              const float* __restrict__ a)
{
    int row = blockIdx.x * 8 + (threadIdx.x >> 5);   // 400 blocks * 8 warps = 3200
    int lane = threadIdx.x & 31;
    const float4* r4 = (const float4*)(Wh + (size_t)row * HH);
    float s1 = 0.f, s2 = 0.f;
    #pragma unroll
    for (int i = 0; i < 6; i++) {
        int c2 = lane + i * 32;
        float4 x = r4[c2];
        float4 u = ((const float4*)a)[c2];
        float4 v = ((const float4*)a)[HH / 4 + c2];
        s1 += x.x * u.x + x.y * u.y + x.z * u.z + x.w * u.w;
        s2 += x.x * v.x + x.y * v.y + x.z * v.z + x.w * v.w;
    }
    #pragma unroll
    for (int o = 16; o; o >>= 1) {
        s1 += __shfl_xor_sync(~0u, s1, o);
        s2 += __shfl_xor_sync(~0u, s2, o);
    }
    if (lane == 0) { g_asrc[row] = s1; g_adst[row] = s2; }
}

// ---------------- 3b) masked softmax rows: one warp per (b,i) --------------
__global__ void softmax_kernel(const float* __restrict__ ab,
                               const int* __restrict__ adj,
                               float* __restrict__ att)
{
    int r = blockIdx.x * 8 + (threadIdx.x >> 5);     // 0..3199
    int lane = threadIdx.x & 31;
    int b = r / NN, i = r % NN;
    float abv = *ab;
    float ai = g_asrc[r];
    int base = b * NN;
    const int* adjr = adj + (size_t)r * NN;          // (b*NN+i)*NN
    int j2 = lane + 32;
    float v0 = ai + g_adst[base + lane] + abv;
    v0 = v0 >= 0.f ? v0 : 0.3f * v0;
    float e0 = (adjr[lane] > 0) ? v0 : -1e30f;
    float e1 = -1e30f;
    if (j2 < NN) {
        float v1 = ai + g_adst[base + j2] + abv;
        v1 = v1 >= 0.f ? v1 : 0.3f * v1;
        e1 = (adjr[j2] > 0) ? v1 : -1e30f;
    }
    float m = fmaxf(e0, e1);
    #pragma unroll
    for (int o = 16; o; o >>= 1) m = fmaxf(m, __shfl_xor_sync(~0u, m, o));
    float x0 = expf(e0 - m);
    float x1 = (j2 < NN) ? expf(e1 - m) : 0.f;
    float s = x0 + x1;
    #pragma unroll
    for (int o = 16; o; o >>= 1) s += __shfl_xor_sync(~0u, s, o);
    float inv = 1.f / s;
    att[(size_t)r * NN + lane] = x0 * inv;
    if (j2 < NN) att[(size_t)r * NN + j2] = x1 * inv;
}

// ------- 4) apply attention: val = elu(att@Wh) (+resid); writes bf16 split --
__global__ __launch_bounds__(256) void gat_apply_kernel(
    const float* __restrict__ att, const float* __restrict__ Wh,
    const float* __restrict__ resid, float* __restrict__ out_f32,
    __nv_bfloat16* __restrict__ hi, __nv_bfloat16* __restrict__ lo)
{
    int b = blockIdx.y, ch = blockIdx.x;       // 6 chunks of 128 cols
    __shared__ float att_s[NN * NN];           // 10 KB
    __shared__ float whs[NN][128];             // 25.6 KB
    int t = threadIdx.x;
    for (int idx = t; idx < NN * NN; idx += 256)
        att_s[idx] = att[(size_t)b * NN * NN + idx];
    const float* whb = Wh + (size_t)b * NN * HH + ch * 128;
    for (int idx = t; idx < NN * 32; idx += 256) {
        int r = idx >> 5, c = (idx & 31) * 4;
        *(float4*)&whs[r][c] = *(const float4*)(whb + (size_t)r * HH + c);
    }
    __syncthreads();
    int hl = t & 127, i0 = t >> 7;
    for (int i = i0; i < NN; i += 4) {
        int ib = (i + 2 < NN) ? i + 2 : i;     // clamp (dup row, store guarded)
        float acc0 = 0.f, acc1 = 0.f;
        #pragma unroll
        for (int j = 0; j < NN; j++) {
            float wv = whs[j][hl];
            acc0 = fmaf(att_s[i * NN + j], wv, acc0);
            acc1 = fmaf(att_s[ib * NN + j], wv, acc1);
        }
        float val0 = acc0 > 0.f ? acc0 : expm1f(acc0);
        size_t off0 = ((size_t)b * NN + i) * HH + ch * 128 + hl;
        if (resid) val0 += resid[off0];
        if (out_f32) out_f32[off0] = val0;
        split1(val0, hi[off0], lo[off0]);
        if (ib != i) {
            float val1 = acc1 > 0.f ? acc1 : expm1f(acc1);
            size_t off1 = ((size_t)b * NN + ib) * HH + ch * 128 + hl;
            if (resid) val1 += resid[off1];
            if (out_f32) out_f32[off1] = val1;
            split1(val1, hi[off1], lo[off1]);
        }
    }
}

// -------- 5) attention pooling -> fp32 D -----------------------------------
__global__ void pool_kernel(const float* __restrict__ T,
                            const float* __restrict__ v,
                            const float* __restrict__ Hres,
                            float* __restrict__ D)
{
    int b = blockIdx.x;
    int t = threadIdx.x, lane = t & 31, w = t >> 5;
    __shared__ float sc[NN];
    for (int n = w; n < NN; n += 8) {
        const float4* row = (const float4*)(T + ((size_t)b * NN + n) * HH);
        float s = 0.f;
        for (int c2 = lane; c2 < HH / 4; c2 += 32) {
            float4 x = row[c2];
            float4 u = ((const float4*)v)[c2];
            s += tanhf(x.x) * u.x + tanhf(x.y) * u.y +
                 tanhf(x.z) * u.z + tanhf(x.w) * u.w;
        }
        #pragma unroll
        for (int o = 16; o; o >>= 1) s += __shfl_xor_sync(~0u, s, o);
        if (lane == 0) sc[n] = s;
    }
    __syncthreads();
    if (t == 0) {
        float m = -1e30f;
        for (int n = 0; n < NN; n++) m = fmaxf(m, sc[n]);
        float s = 0.f;
        for (int n = 0; n < NN; n++) { sc[n] = expf(sc[n] - m); s += sc[n]; }
        float inv = 1.f / s;
        for (int n = 0; n < NN; n++) sc[n] *= inv;
    }
    __syncthreads();
    for (int h = t; h < HH; h += 256) {
        float acc = 0.f;
        #pragma unroll 5
        for (int n = 0; n < NN; n++)
            acc = fmaf(sc[n], Hres[((size_t)b * NN + n) * HH + h], acc);
        D[(size_t)b * HH + h] = acc;
    }
}

// -------- 6) final linear: out[64,768] = D @ Wl + bl (fp32, wide grid) -----
__global__ __launch_bounds__(128) void final_linear_kernel(
    const float* __restrict__ D, const float* __restrict__ W,
    const float* __restrict__ bias, float* __restrict__ out)
{
    int b = blockIdx.y;
    int o = blockIdx.x * 128 + threadIdx.x;
    __shared__ float Ds[HH];
    for (int i = threadIdx.x; i < HH; i += 128)
        Ds[i] = D[(size_t)b * HH + i];
    __syncthreads();
    float acc = 0.f;
    #pragma unroll 8
    for (int h = 0; h < HH; h++)
        acc = fmaf(Ds[h], W[(size_t)h * OO + o], acc);
    out[(size_t)b * OO + o] = acc + bias[o];
}

// ---------------- launch ----------------------------------------------------
extern "C" void kernel_launch(void* const* d_in, const int* in_sizes, int n_in,
                              void* d_out, int out_size)
{
    const float* emb = (const float*)d_in[0];
    const int*   ids = (const int*)  d_in[1];
    const int*   adj = (const int*)  d_in[2];
    const float* W1  = (const float*)d_in[3];
    const float* b1  = (const float*)d_in[4];
    const float* a1  = (const float*)d_in[5];
    const float* ab1 = (const float*)d_in[6];
    const float* W2  = (const float*)d_in[7];
    const float* b2  = (const float*)d_in[8];
    const float* a2  = (const float*)d_in[9];
    const float* ab2 = (const float*)d_in[10];
    const float* Wa  = (const float*)d_in[11];
    const float* ba  = (const float*)d_in[12];
    const float* v   = (const float*)d_in[13];
    const float* Wl  = (const float*)d_in[14];
    const float* bl  = (const float*)d_in[15];
    float* out = (float*)d_out;

    void *pX, *pWh, *pHres, *pT, *pAtt, *pD, *pAh, *pAl, *pBh, *pBl;
    cudaGetSymbolAddress(&pX, g_X);
    cudaGetSymbolAddress(&pWh, g_Wh);
    cudaGetSymbolAddress(&pHres, g_Hres);
    cudaGetSymbolAddress(&pT, g_T);
    cudaGetSymbolAddress(&pAtt, g_att);
    cudaGetSymbolAddress(&pD, g_D);
    cudaGetSymbolAddress(&pAh, g_Ah);
    cudaGetSymbolAddress(&pAl, g_Al);
    cudaGetSymbolAddress(&pBh, g_Bh);
    cudaGetSymbolAddress(&pBl, g_Bl);
    float* X    = (float*)pX;
    float* Wh   = (float*)pWh;
    float* Hres = (float*)pHres;
    float* T    = (float*)pT;
    float* Att  = (float*)pAtt;
    float* D    = (float*)pD;
    __nv_bfloat16* Ah = (__nv_bfloat16*)pAh;
    __nv_bfloat16* Al = (__nv_bfloat16*)pAl;
    __nv_bfloat16* Bh = (__nv_bfloat16*)pBh;
    __nv_bfloat16* Bl = (__nv_bfloat16*)pBl;
    const size_t WSZ = (size_t)HH * HH;

    cudaFuncSetAttribute(gemm_bf16x3,
                         cudaFuncAttributeMaxDynamicSharedMemorySize, SMEM_BYTES);

    dim3 ggemm(HH / 128, MTOT / 128);   // (6, 25)
    dim3 gapply(HH / 128, BB);
    dim3 gsplitw((HH * HH / 4 + 255) / 256, 3);
    dim3 gfinal(OO / 128, BB);          // (6, 64)

    // 0) weights -> bf16 splits (W1,W2,Wa)
    split_weights_kernel<<<gsplitw, 256>>>(W1, W2, Wa);
    // 1) gather + PE (+ split of X)
    gather_pe_kernel<<<MTOT, HH / 4>>>(emb, ids);
    // 2) Wh1 = X @ W1 + b1
    gemm_bf16x3<<<ggemm, 256, SMEM_BYTES>>>(Ah, Al, Bh, Bl, b1, Wh, MTOT);
    // 3) GAT layer 1: scores + softmax + apply (elu) -> split(H1) only
    scores_kernel<<<MTOT / 8, 256>>>(Wh, a1);
    softmax_kernel<<<MTOT / 8, 256>>>(ab1, adj, Att);
    gat_apply_kernel<<<gapply, 256>>>(Att, Wh, nullptr, nullptr, Ah, Al);
    // 4) Wh2 = H1 @ W2 + b2
    gemm_bf16x3<<<ggemm, 256, SMEM_BYTES>>>(Ah, Al, Bh + WSZ, Bl + WSZ, b2, Wh, MTOT);
    // 5) GAT layer 2: scores + softmax + apply (elu + residual X)
    scores_kernel<<<MTOT / 8, 256>>>(Wh, a2);
    softmax_kernel<<<MTOT / 8, 256>>>(ab2, adj, Att);
    gat_apply_kernel<<<gapply, 256>>>(Att, Wh, X, Hres, Ah, Al);
    // 6) T = Hres @ Wa + ba
    gemm_bf16x3<<<ggemm, 256, SMEM_BYTES>>>(Ah, Al, Bh + 2*WSZ, Bl + 2*WSZ, ba, T, MTOT);
    // 7) attention pooling -> fp32 D
    pool_kernel<<<BB, 256>>>(T, v, Hres, D);
    // 8) out = D @ Wl + bl (fp32, wide grid)
    final_linear_kernel<<<gfinal, 128>>>(D, Wl, bl, out);
}

// round 7
// speedup vs baseline: 2.2876x; 1.0253x over previous
#include <cuda_runtime.h>
#include <cuda_bf16.h>
#include <math.h>

#define BB 64
#define LL 512
#define HH 768
#define NN 50
#define OO 768
#define MTOT (BB*NN)   // 3200

// ---------------- scratch (device globals; no allocations allowed) ----------
__device__ float g_X[MTOT*HH];     // gathered + positional-encoded input (fp32, residual)
__device__ float g_Wh[MTOT*HH];    // Wh of current GAT layer
__device__ float g_Hres[MTOT*HH];  // elu(gat2) + X (fp32, needed by pool)
__device__ float g_T[MTOT*HH];     // Hres@Wa + ba
__device__ float g_sp1[12*MTOT];   // partial a_src sums (per bn x warp_n)
__device__ float g_sp2[12*MTOT];   // partial a_dst sums
__device__ float g_D[BB*HH];       // pooled dialogue vectors (fp32)
// bf16 split buffers
__device__ __nv_bfloat16 g_Ah[MTOT*HH];
__device__ __nv_bfloat16 g_Al[MTOT*HH];
__device__ __nv_bfloat16 g_Bh[3*HH*HH];   // W1,W2,Wa hi
__device__ __nv_bfloat16 g_Bl[3*HH*HH];   // W1,W2,Wa lo

__device__ __forceinline__ void split1(float v, __nv_bfloat16& h, __nv_bfloat16& l) {
    h = __float2bfloat16(v);
    l = __float2bfloat16(v - __bfloat162float(h));
}

// ---------------- 0) split the 3 mma weight matrices (one launch) ----------
__global__ void split_weights_kernel(const float* __restrict__ w0,
                                     const float* __restrict__ w1,
                                     const float* __restrict__ w2)
{
    const float* srcs[3] = {w0, w1, w2};
    int m = blockIdx.y;
    int i = blockIdx.x * blockDim.x + threadIdx.x;   // float4 index
    const int n4 = HH * HH / 4;
    if (i >= n4) return;
    float4 v = ((const float4*)srcs[m])[i];
    __nv_bfloat16 h0,h1,h2,h3,l0,l1,l2,l3;
    split1(v.x,h0,l0); split1(v.y,h1,l1); split1(v.z,h2,l2); split1(v.w,h3,l3);
    __nv_bfloat162* H = (__nv_bfloat162*)(g_Bh + (size_t)m * HH * HH);
    __nv_bfloat162* L = (__nv_bfloat162*)(g_Bl + (size_t)m * HH * HH);
    H[2*i]   = __nv_bfloat162(h0,h1);
    H[2*i+1] = __nv_bfloat162(h2,h3);
    L[2*i]   = __nv_bfloat162(l0,l1);
    L[2*i+1] = __nv_bfloat162(l2,l3);
}

// ---------------- 1) gather + sinusoidal PE (+ bf16 split of X) ------------
__global__ void gather_pe_kernel(const float* __restrict__ emb,
                                 const int* __restrict__ ids)
{
    int bn = blockIdx.x;            // 0..3199
    int b = bn / NN, n = bn % NN;
    int h = threadIdx.x * 4;        // 192 threads * 4 = 768
    int id = ids[bn];
    float4 e = *(const float4*)(emb + ((size_t)b * LL + id) * HH + h);
    const float c = -logf(10000.0f) / (float)HH;
    float d0 = expf((float)h * c);
    float d1 = expf((float)(h + 2) * c);
    float a0 = (float)n * d0, a1 = (float)n * d1;
    e.x += sinf(a0); e.y += cosf(a0);
    e.z += sinf(a1); e.w += cosf(a1);
    size_t off = (size_t)bn * HH + h;
    *(float4*)(g_X + off) = e;
    __nv_bfloat16 h0,h1,h2,h3,l0,l1,l2,l3;
    split1(e.x,h0,l0); split1(e.y,h1,l1); split1(e.z,h2,l2); split1(e.w,h3,l3);
    *(__nv_bfloat162*)(g_Ah + off)     = __nv_bfloat162(h0,h1);
    *(__nv_bfloat162*)(g_Ah + off + 2) = __nv_bfloat162(h2,h3);
    *(__nv_bfloat162*)(g_Al + off)     = __nv_bfloat162(l0,l1);
    *(__nv_bfloat162*)(g_Al + off + 2) = __nv_bfloat162(l2,l3);
}

// ---------------- tensor-core GEMM (bf16x3 split, fp32 accum) --------------
// C[M,768] = A[M,768] @ W[768,768] + bias.  K-chunk 64, 2-stage cp.async.
// If avec != null, also emits partial GAT scores (C-row dot avec[:768] and
// avec[768:]) into g_sp1/g_sp2 slot (blockIdx.x*2 + warp_n).
#define KC 64
#define SA_ELEMS (2*128*72)                 // 18432
#define SB_ELEMS (2*64*136)                 // 17408
#define STAGE_ELEMS (SA_ELEMS + SB_ELEMS)   // 35840
#define SA_IDX(st,sp,r,c) ((size_t)(st)*STAGE_ELEMS + ((sp)*128 + (r))*72 + (c))
#define SB_IDX(st,sp,r,c) ((size_t)(st)*STAGE_ELEMS + SA_ELEMS + ((sp)*64 + (r))*136 + (c))
#define SMEM_BYTES (2 * STAGE_ELEMS * 2)    // 143360 B

#define CP16(dst, src) \
    asm volatile("cp.async.cg.shared.global [%0], [%1], 16;\n" :: "r"(dst), "l"(src))

__device__ __forceinline__ void ldsm4(unsigned* r, const void* p) {
    unsigned addr = (unsigned)__cvta_generic_to_shared(p);
    asm volatile("ldmatrix.sync.aligned.m8n8.x4.shared.b16 {%0,%1,%2,%3}, [%4];\n"
                 : "=r"(r[0]), "=r"(r[1]), "=r"(r[2]), "=r"(r[3]) : "r"(addr));
}
__device__ __forceinline__ void ldsm4t(unsigned* r, const void* p) {
    unsigned addr = (unsigned)__cvta_generic_to_shared(p);
    asm volatile("ldmatrix.sync.aligned.m8n8.x4.trans.shared.b16 {%0,%1,%2,%3}, [%4];\n"
                 : "=r"(r[0]), "=r"(r[1]), "=r"(r[2]), "=r"(r[3]) : "r"(addr));
}
__device__ __forceinline__ void mma16816(float* c, const unsigned* a, const unsigned* b) {
    asm volatile("mma.sync.aligned.m16n8k16.row.col.f32.bf16.bf16.f32 "
                 "{%0,%1,%2,%3}, {%4,%5,%6,%7}, {%8,%9}, {%0,%1,%2,%3};\n"
                 : "+f"(c[0]), "+f"(c[1]), "+f"(c[2]), "+f"(c[3])
                 : "r"(a[0]), "r"(a[1]), "r"(a[2]), "r"(a[3]),
                   "r"(b[0]), "r"(b[1]));
}

__global__ __launch_bounds__(256, 1) void gemm_bf16x3(
    const __nv_bfloat16* __restrict__ Ah, const __nv_bfloat16* __restrict__ Al,
    const __nv_bfloat16* __restrict__ Bh, const __nv_bfloat16* __restrict__ Bl,
    const float* __restrict__ bias, float* __restrict__ C, int M,
    const float* __restrict__ avec)
{
    extern __shared__ __nv_bfloat16 sm[];
    const int tid = threadIdx.x;
    const int lane = tid & 31, wid = tid >> 5;
    const int warp_m = wid >> 1, warp_n = wid & 1;
    const int bm = blockIdx.y * 128, bn = blockIdx.x * 128;

    const int arA = tid >> 1, acA = (tid & 1) * 8;   // A: 128 rows, 4 col passes
    const int brB = tid >> 4, bcB = (tid & 15) * 8;  // B: 16 rows/pass, 4 passes
    const int rA = min(bm + arA, M - 1);             // clamp (masked at store)

    float acc[2][8][4] = {};
    const __nv_bfloat16* As[2] = {Ah, Al};
    const __nv_bfloat16* Bs[2] = {Bh, Bl};

    auto load_stage = [&](int st, int k0) {
        #pragma unroll
        for (int s = 0; s < 2; s++) {
            const __nv_bfloat16* ag = As[s] + (size_t)rA * HH + k0;
            #pragma unroll
            for (int p = 0; p < 4; p++) {
                int col = acA + p * 16;
                unsigned d = (unsigned)__cvta_generic_to_shared(&sm[SA_IDX(st, s, arA, col)]);
                CP16(d, ag + col);
            }
            #pragma unroll
            for (int p = 0; p < 4; p++) {
                int row = brB + p * 16;
                unsigned e = (unsigned)__cvta_generic_to_shared(&sm[SB_IDX(st, s, row, bcB)]);
                CP16(e, Bs[s] + (size_t)(k0 + row) * HH + bn + bcB);
            }
        }
        asm volatile("cp.async.commit_group;\n" ::: "memory");
    };

    load_stage(0, 0);

    const int lrow = lane & 15, lcol = (lane >> 4) * 8;
    const int NCH = HH / KC;   // 12

    for (int c = 0; c < NCH; c++) {
        asm volatile("cp.async.wait_group 0;\n" ::: "memory");
        __syncthreads();
        if (c + 1 < NCH) load_stage((c + 1) & 1, (c + 1) * KC);
        const int st = c & 1;

        #pragma unroll
        for (int ks = 0; ks < 4; ks++) {
            const int kb = ks * 16;
            unsigned a[2][2][4];
            #pragma unroll
            for (int mt = 0; mt < 2; mt++)
                #pragma unroll
                for (int s = 0; s < 2; s++)
                    ldsm4(a[s][mt], &sm[SA_IDX(st, s, warp_m * 32 + mt * 16 + lrow, kb + lcol)]);
            unsigned b[2][8][2];
            #pragma unroll
            for (int g = 0; g < 4; g++)
                #pragma unroll
                for (int s = 0; s < 2; s++) {
                    unsigned r[4];
                    ldsm4t(r, &sm[SB_IDX(st, s, kb + lrow, warp_n * 64 + g * 16 + lcol)]);
                    b[s][2*g][0]   = r[0]; b[s][2*g][1]   = r[1];
                    b[s][2*g+1][0] = r[2]; b[s][2*g+1][1] = r[3];
                }
            #pragma unroll
            for (int mt = 0; mt < 2; mt++)
                #pragma unroll
                for (int nt = 0; nt < 8; nt++) {
                    mma16816(acc[mt][nt], a[0][mt], b[0][nt]);
                    mma16816(acc[mt][nt], a[0][mt], b[1][nt]);
                    mma16816(acc[mt][nt], a[1][mt], b[0][nt]);
                }
        }
    }

    // ---- epilogue: bias add, fp32 store, optional fused score partials ----
    const int er = bm + warp_m * 32 + (lane >> 2);
    const int ec = bn + warp_n * 64 + (lane & 3) * 2;
    float p1[2][2] = {}, p2[2][2] = {};   // [mt][rowhalf]
    #pragma unroll
    for (int mt = 0; mt < 2; mt++)
        #pragma unroll
        for (int nt = 0; nt < 8; nt++) {
            int r = er + mt * 16;
            int cc = ec + nt * 8;
            float b0 = bias[cc], b1 = bias[cc + 1];
            float v00 = acc[mt][nt][0] + b0, v01 = acc[mt][nt][1] + b1;
            float v10 = acc[mt][nt][2] + b0, v11 = acc[mt][nt][3] + b1;
            if (r < M) {
                C[(size_t)r * HH + cc]     = v00;
                C[(size_t)r * HH + cc + 1] = v01;
            }
            if (r + 8 < M) {
                C[(size_t)(r + 8) * HH + cc]     = v10;
                C[(size_t)(r + 8) * HH + cc + 1] = v11;
            }
            if (avec) {
                float au0 = avec[cc], au1 = avec[cc + 1];
                float av0 = avec[HH + cc], av1 = avec[HH + cc + 1];
                p1[mt][0] += v00 * au0 + v01 * au1;
                p2[mt][0] += v00 * av0 + v01 * av1;
                p1[mt][1] += v10 * au0 + v11 * au1;
                p2[mt][1] += v10 * av0 + v11 * av1;
            }
        }
    if (avec) {
        #pragma unroll
        for (int mt = 0; mt < 2; mt++)
            #pragma unroll
            for (int h = 0; h < 2; h++) {
                #pragma unroll
                for (int o = 1; o <= 2; o <<= 1) {
                    p1[mt][h] += __shfl_xor_sync(~0u, p1[mt][h], o);
                    p2[mt][h] += __shfl_xor_sync(~0u, p2[mt][h], o);
                }
            }
        if ((lane & 3) == 0) {
            int slot = blockIdx.x * 2 + warp_n;
            #pragma unroll
            for (int mt = 0; mt < 2; mt++)
                #pragma unroll
                for (int h = 0; h < 2; h++) {
                    int r = er + mt * 16 + h * 8;
                    if (r < M) {
                        g_sp1[(size_t)slot * MTOT + r] = p1[mt][h];
                        g_sp2[(size_t)slot * MTOT + r] = p2[mt][h];
                    }
                }
        }
    }
}

// -- 3) fused GAT tail: reduce score partials, masked softmax, apply, elu ---
__global__ __launch_bounds__(256) void gat_apply_kernel(
    const float* __restrict__ Wh, const int* __restrict__ adj,
    const float* __restrict__ ab,
    const float* __restrict__ resid, float* __restrict__ out_f32,
    __nv_bfloat16* __restrict__ hi, __nv_bfloat16* __restrict__ lo)
{
    int b = blockIdx.y, ch = blockIdx.x;       // 6 chunks of 128 cols
    __shared__ float att_s[NN * NN];           // 10 KB
    __shared__ float whs[NN][128];             // 25.6 KB
    __shared__ float asrc_s[NN], adst_s[NN];
    int t = threadIdx.x;
    int lane = t & 31, w = t >> 5;

    // load Wh chunk
    const float* whb = Wh + (size_t)b * NN * HH + ch * 128;
    for (int idx = t; idx < NN * 32; idx += 256) {
        int r = idx >> 5, c = (idx & 31) * 4;
        *(float4*)&whs[r][c] = *(const float4*)(whb + (size_t)r * HH + c);
    }
    // reduce the 12 score partials
    if (t < 2 * NN) {
        int i = t % NN;
        const float* sp = (t < NN) ? g_sp1 : g_sp2;
        float s = 0.f;
        #pragma unroll
        for (int c = 0; c < 12; c++) s += sp[(size_t)c * MTOT + b * NN + i];
        ((t < NN) ? asrc_s : adst_s)[i] = s;
    }
    __syncthreads();

    // masked softmax rows -> att_s (one warp per row)
    float abv = *ab;
    for (int i = w; i < NN; i += 8) {
        float ai = asrc_s[i];
        const int* adjr = adj + ((size_t)b * NN + i) * NN;
        int j2 = lane + 32;
        float v0 = ai + adst_s[lane] + abv;
        v0 = v0 >= 0.f ? v0 : 0.3f * v0;
        float e0 = (adjr[lane] > 0) ? v0 : -1e30f;
        float e1 = -1e30f;
        if (j2 < NN) {
            float v1 = ai + adst_s[j2] + abv;
            v1 = v1 >= 0.f ? v1 : 0.3f * v1;
            e1 = (adjr[j2] > 0) ? v1 : -1e30f;
        }
        float m = fmaxf(e0, e1);
        #pragma unroll
        for (int o = 16; o; o >>= 1) m = fmaxf(m, __shfl_xor_sync(~0u, m, o));
        float x0 = expf(e0 - m);
        float x1 = (j2 < NN) ? expf(e1 - m) : 0.f;
        float s = x0 + x1;
        #pragma unroll
        for (int o = 16; o; o >>= 1) s += __shfl_xor_sync(~0u, s, o);
        float inv = 1.f / s;
        att_s[i * NN + lane] = x0 * inv;
        if (j2 < NN) att_s[i * NN + j2] = x1 * inv;
    }
    __syncthreads();

    // apply: 4 rows per thread per pass
    int hl = t & 127, i0 = (t >> 7) * 4;
    for (int ibase = 0; ibase < NN; ibase += 8) {
        int r0 = ibase + i0;
        if (r0 >= NN) break;
        int rk0 = r0, rk1 = min(r0 + 1, NN - 1),
            rk2 = min(r0 + 2, NN - 1), rk3 = min(r0 + 3, NN - 1);
        float a0 = 0.f, a1 = 0.f, a2 = 0.f, a3 = 0.f;
        #pragma unroll
        for (int j = 0; j < NN; j++) {
            float wv = whs[j][hl];
            a0 = fmaf(att_s[rk0 * NN + j], wv, a0);
            a1 = fmaf(att_s[rk1 * NN + j], wv, a1);
            a2 = fmaf(att_s[rk2 * NN + j], wv, a2);
            a3 = fmaf(att_s[rk3 * NN + j], wv, a3);
        }
        float vals[4] = {a0, a1, a2, a3};
        #pragma unroll
        for (int k = 0; k < 4; k++) {
            int row = r0 + k;
            if (row >= NN) break;
            float val = vals[k] > 0.f ? vals[k] : expm1f(vals[k]);
            size_t off = ((size_t)b * NN + row) * HH + ch * 128 + hl;
            if (resid) val += resid[off];
            if (out_f32) out_f32[off] = val;
            split1(val, hi[off], lo[off]);
        }
    }
}

// -------- 5) attention pooling -> fp32 D -----------------------------------
__global__ void pool_kernel(const float* __restrict__ T,
                            const float* __restrict__ v,
                            const float* __restrict__ Hres,
                            float* __restrict__ D)
{
    int b = blockIdx.x;
    int t = threadIdx.x, lane = t & 31, w = t >> 5;
    __shared__ float sc[NN];
    for (int n = w; n < NN; n += 8) {
        const float4* row = (const float4*)(T + ((size_t)b * NN + n) * HH);
        float s = 0.f;
        for (int c2 = lane; c2 < HH / 4; c2 += 32) {
            float4 x = row[c2];
            float4 u = ((const float4*)v)[c2];
            s += tanhf(x.x) * u.x + tanhf(x.y) * u.y +
                 tanhf(x.z) * u.z + tanhf(x.w) * u.w;
        }
        #pragma unroll
        for (int o = 16; o; o >>= 1) s += __shfl_xor_sync(~0u, s, o);
        if (lane == 0) sc[n] = s;
    }
    __syncthreads();
    if (t == 0) {
        float m = -1e30f;
        for (int n = 0; n < NN; n++) m = fmaxf(m, sc[n]);
        float s = 0.f;
        for (int n = 0; n < NN; n++) { sc[n] = expf(sc[n] - m); s += sc[n]; }
        float inv = 1.f / s;
        for (int n = 0; n < NN; n++) sc[n] *= inv;
    }
    __syncthreads();
    for (int h = t; h < HH; h += 256) {
        float acc = 0.f;
        #pragma unroll 5
        for (int n = 0; n < NN; n++)
            acc = fmaf(sc[n], Hres[((size_t)b * NN + n) * HH + h], acc);
        D[(size_t)b * HH + h] = acc;
    }
}

// -------- 6) final linear: out[64,768] = D @ Wl + bl (fp32, wide grid) -----
__global__ __launch_bounds__(128) void final_linear_kernel(
    const float* __restrict__ D, const float* __restrict__ W,
    const float* __restrict__ bias, float* __restrict__ out)
{
    int b = blockIdx.y;
    int o = blockIdx.x * 128 + threadIdx.x;
    __shared__ float Ds[HH];
    for (int i = threadIdx.x; i < HH; i += 128)
        Ds[i] = D[(size_t)b * HH + i];
    __syncthreads();
    float acc = 0.f;
    #pragma unroll 8
    for (int h = 0; h < HH; h++)
        acc = fmaf(Ds[h], W[(size_t)h * OO + o], acc);
    out[(size_t)b * OO + o] = acc + bias[o];
}

// ---------------- launch ----------------------------------------------------
extern "C" void kernel_launch(void* const* d_in, const int* in_sizes, int n_in,
                              void* d_out, int out_size)
{
    const float* emb = (const float*)d_in[0];
    const int*   ids = (const int*)  d_in[1];
    const int*   adj = (const int*)  d_in[2];
    const float* W1  = (const float*)d_in[3];
    const float* b1  = (const float*)d_in[4];
    const float* a1  = (const float*)d_in[5];
    const float* ab1 = (const float*)d_in[6];
    const float* W2  = (const float*)d_in[7];
    const float* b2  = (const float*)d_in[8];
    const float* a2  = (const float*)d_in[9];
    const float* ab2 = (const float*)d_in[10];
    const float* Wa  = (const float*)d_in[11];
    const float* ba  = (const float*)d_in[12];
    const float* v   = (const float*)d_in[13];
    const float* Wl  = (const float*)d_in[14];
    const float* bl  = (const float*)d_in[15];
    float* out = (float*)d_out;

    void *pX, *pWh, *pHres, *pT, *pD, *pAh, *pAl, *pBh, *pBl;
    cudaGetSymbolAddress(&pX, g_X);
    cudaGetSymbolAddress(&pWh, g_Wh);
    cudaGetSymbolAddress(&pHres, g_Hres);
    cudaGetSymbolAddress(&pT, g_T);
    cudaGetSymbolAddress(&pD, g_D);
    cudaGetSymbolAddress(&pAh, g_Ah);
    cudaGetSymbolAddress(&pAl, g_Al);
    cudaGetSymbolAddress(&pBh, g_Bh);
    cudaGetSymbolAddress(&pBl, g_Bl);
    float* X    = (float*)pX;
    float* Wh   = (float*)pWh;
    float* Hres = (float*)pHres;
    float* T    = (float*)pT;
    float* D    = (float*)pD;
    __nv_bfloat16* Ah = (__nv_bfloat16*)pAh;
    __nv_bfloat16* Al = (__nv_bfloat16*)pAl;
    __nv_bfloat16* Bh = (__nv_bfloat16*)pBh;
    __nv_bfloat16* Bl = (__nv_bfloat16*)pBl;
    const size_t WSZ = (size_t)HH * HH;

    cudaFuncSetAttribute(gemm_bf16x3,
                         cudaFuncAttributeMaxDynamicSharedMemorySize, SMEM_BYTES);

    dim3 ggemm(HH / 128, MTOT / 128);   // (6, 25)
    dim3 gapply(HH / 128, BB);          // (6, 64)
    dim3 gsplitw((HH * HH / 4 + 255) / 256, 3);
    dim3 gfinal(OO / 128, BB);          // (6, 64)

    // 0) weights -> bf16 splits (W1,W2,Wa)
    split_weights_kernel<<<gsplitw, 256>>>(W1, W2, Wa);
    // 1) gather + PE (+ split of X)
    gather_pe_kernel<<<MTOT, HH / 4>>>(emb, ids);
    // 2) Wh1 = X @ W1 + b1  (+ fused a1 score partials)
    gemm_bf16x3<<<ggemm, 256, SMEM_BYTES>>>(Ah, Al, Bh, Bl, b1, Wh, MTOT, a1);
    // 3) GAT layer 1 tail: reduce partials + softmax + apply (elu) -> split(H1)
    gat_apply_kernel<<<gapply, 256>>>(Wh, adj, ab1, nullptr, nullptr, Ah, Al);
    // 4) Wh2 = H1 @ W2 + b2 (+ fused a2 score partials)
    gemm_bf16x3<<<ggemm, 256, SMEM_BYTES>>>(Ah, Al, Bh + WSZ, Bl + WSZ, b2, Wh, MTOT, a2);
    // 5) GAT layer 2 tail: softmax + apply (elu + residual X) -> Hres + split
    gat_apply_kernel<<<gapply, 256>>>(Wh, adj, ab2, X, Hres, Ah, Al);
    // 6) T = Hres @ Wa + ba
    gemm_bf16x3<<<ggemm, 256, SMEM_BYTES>>>(Ah, Al, Bh + 2*WSZ, Bl + 2*WSZ, ba, T, MTOT, nullptr);
    // 7) attention pooling -> fp32 D
    pool_kernel<<<BB, 256>>>(T, v, Hres, D);
    // 8) out = D @ Wl + bl (fp32, wide grid)
    final_linear_kernel<<<gfinal, 128>>>(D, Wl, bl, out);
}

// round 8
// speedup vs baseline: 2.4126x; 1.0546x over previous
#include <cuda_runtime.h>
#include <cuda_bf16.h>
#include <math.h>

#define BB 64
#define LL 512
#define HH 768
#define NN 50
#define OO 768
#define MTOT (BB*NN)   // 3200

// ---------------- scratch (device globals; no allocations allowed) ----------
__device__ float g_X[MTOT*HH];
__device__ float g_Wh[MTOT*HH];
__device__ float g_Hres[MTOT*HH];
__device__ float g_T[MTOT*HH];
__device__ float g_sp1[12*MTOT];   // partial a_src sums (per bn x warp_n)
__device__ float g_sp2[12*MTOT];   // partial a_dst sums
__device__ float g_D[BB*HH];
__device__ __nv_bfloat16 g_Ah[MTOT*HH];
__device__ __nv_bfloat16 g_Al[MTOT*HH];
__device__ __nv_bfloat16 g_Bh[3*HH*HH];   // W1,W2,Wa hi
__device__ __nv_bfloat16 g_Bl[3*HH*HH];   // W1,W2,Wa lo

__device__ __forceinline__ void split1(float v, __nv_bfloat16& h, __nv_bfloat16& l) {
    h = __float2bfloat16(v);
    l = __float2bfloat16(v - __bfloat162float(h));
}
__device__ __forceinline__ unsigned long long pack2(float x, float y) {
    unsigned long long r;
    asm("mov.b64 %0, {%1, %2};" : "=l"(r) : "f"(x), "f"(y));
    return r;
}
__device__ __forceinline__ void unpack2(unsigned long long v, float& x, float& y) {
    asm("mov.b64 {%0, %1}, %2;" : "=f"(x), "=f"(y) : "l"(v));
}
__device__ __forceinline__ void ffma2(unsigned long long& acc,
                                      unsigned long long a, unsigned long long b) {
    asm("fma.rn.f32x2 %0, %1, %2, %0;" : "+l"(acc) : "l"(a), "l"(b));
}

// ---------------- 0) split the 3 mma weight matrices -----------------------
__global__ void split_weights_kernel(const float* __restrict__ w0,
                                     const float* __restrict__ w1,
                                     const float* __restrict__ w2)
{
    const float* srcs[3] = {w0, w1, w2};
    int m = blockIdx.y;
    int i = blockIdx.x * blockDim.x + threadIdx.x;
    const int n4 = HH * HH / 4;
    if (i >= n4) return;
    float4 v = ((const float4*)srcs[m])[i];
    __nv_bfloat16 h0,h1,h2,h3,l0,l1,l2,l3;
    split1(v.x,h0,l0); split1(v.y,h1,l1); split1(v.z,h2,l2); split1(v.w,h3,l3);
    __nv_bfloat162* H = (__nv_bfloat162*)(g_Bh + (size_t)m * HH * HH);
    __nv_bfloat162* L = (__nv_bfloat162*)(g_Bl + (size_t)m * HH * HH);
    H[2*i]   = __nv_bfloat162(h0,h1);
    H[2*i+1] = __nv_bfloat162(h2,h3);
    L[2*i]   = __nv_bfloat162(l0,l1);
    L[2*i+1] = __nv_bfloat162(l2,l3);
}

// ---------------- 1) gather + sinusoidal PE (+ bf16 split of X) ------------
__global__ void gather_pe_kernel(const float* __restrict__ emb,
                                 const int* __restrict__ ids)
{
    int bn = blockIdx.x;
    int b = bn / NN, n = bn % NN;
    int h = threadIdx.x * 4;
    int id = ids[bn];
    float4 e = *(const float4*)(emb + ((size_t)b * LL + id) * HH + h);
    const float c = -logf(10000.0f) / (float)HH;
    float d0 = expf((float)h * c);
    float d1 = expf((float)(h + 2) * c);
    float a0 = (float)n * d0, a1 = (float)n * d1;
    e.x += sinf(a0); e.y += cosf(a0);
    e.z += sinf(a1); e.w += cosf(a1);
    size_t off = (size_t)bn * HH + h;
    *(float4*)(g_X + off) = e;
    __nv_bfloat16 h0,h1,h2,h3,l0,l1,l2,l3;
    split1(e.x,h0,l0); split1(e.y,h1,l1); split1(e.z,h2,l2); split1(e.w,h3,l3);
    *(__nv_bfloat162*)(g_Ah + off)     = __nv_bfloat162(h0,h1);
    *(__nv_bfloat162*)(g_Ah + off + 2) = __nv_bfloat162(h2,h3);
    *(__nv_bfloat162*)(g_Al + off)     = __nv_bfloat162(l0,l1);
    *(__nv_bfloat162*)(g_Al + off + 2) = __nv_bfloat162(l2,l3);
}

// ---------------- tensor-core GEMM (bf16x3 split, fp32 accum) --------------
// KC=32, 2-stage, 2 CTAs/SM. Optional fused GAT score partials.
#define KC 32
#define SA_ELEMS (2*128*40)                 // 10240
#define SB_ELEMS (2*32*136)                 // 8704
#define STAGE_ELEMS (SA_ELEMS + SB_ELEMS)   // 18944
#define SA_IDX(st,sp,r,c) ((size_t)(st)*STAGE_ELEMS + ((sp)*128 + (r))*40 + (c))
#define SB_IDX(st,sp,r,c) ((size_t)(st)*STAGE_ELEMS + SA_ELEMS + ((sp)*32 + (r))*136 + (c))
#define SMEM_BYTES (2 * STAGE_ELEMS * 2)    // 75776 B

#define CP16(dst, src) \
    asm volatile("cp.async.cg.shared.global [%0], [%1], 16;\n" :: "r"(dst), "l"(src))

__device__ __forceinline__ void ldsm4(unsigned* r, const void* p) {
    unsigned addr = (unsigned)__cvta_generic_to_shared(p);
    asm volatile("ldmatrix.sync.aligned.m8n8.x4.shared.b16 {%0,%1,%2,%3}, [%4];\n"
                 : "=r"(r[0]), "=r"(r[1]), "=r"(r[2]), "=r"(r[3]) : "r"(addr));
}
__device__ __forceinline__ void ldsm4t(unsigned* r, const void* p) {
    unsigned addr = (unsigned)__cvta_generic_to_shared(p);
    asm volatile("ldmatrix.sync.aligned.m8n8.x4.trans.shared.b16 {%0,%1,%2,%3}, [%4];\n"
                 : "=r"(r[0]), "=r"(r[1]), "=r"(r[2]), "=r"(r[3]) : "r"(addr));
}
__device__ __forceinline__ void mma16816(float* c, const unsigned* a, const unsigned* b) {
    asm volatile("mma.sync.aligned.m16n8k16.row.col.f32.bf16.bf16.f32 "
                 "{%0,%1,%2,%3}, {%4,%5,%6,%7}, {%8,%9}, {%0,%1,%2,%3};\n"
                 : "+f"(c[0]), "+f"(c[1]), "+f"(c[2]), "+f"(c[3])
                 : "r"(a[0]), "r"(a[1]), "r"(a[2]), "r"(a[3]),
                   "r"(b[0]), "r"(b[1]));
}

__global__ __launch_bounds__(256, 2) void gemm_bf16x3(
    const __nv_bfloat16* __restrict__ Ah, const __nv_bfloat16* __restrict__ Al,
    const __nv_bfloat16* __restrict__ Bh, const __nv_bfloat16* __restrict__ Bl,
    const float* __restrict__ bias, float* __restrict__ C, int M,
    const float* __restrict__ avec)
{
    extern __shared__ __nv_bfloat16 sm[];
    const int tid = threadIdx.x;
    const int lane = tid & 31, wid = tid >> 5;
    const int warp_m = wid >> 1, warp_n = wid & 1;
    const int bm = blockIdx.y * 128, bn = blockIdx.x * 128;

    const int ar = tid >> 2, ac = (tid & 3) * 8;    // A: 64 rows/pass
    const int br = tid >> 4, bc = (tid & 15) * 8;   // B: 16 rows/pass
    const int rA0 = min(bm + ar, M - 1);            // clamp (masked at store)
    const int rA1 = min(bm + ar + 64, M - 1);

    float acc[2][8][4] = {};
    const __nv_bfloat16* As[2] = {Ah, Al};
    const __nv_bfloat16* Bs[2] = {Bh, Bl};

    auto load_stage = [&](int st, int k0) {
        #pragma unroll
        for (int s = 0; s < 2; s++) {
            unsigned d0 = (unsigned)__cvta_generic_to_shared(&sm[SA_IDX(st, s, ar, ac)]);
            CP16(d0, As[s] + (size_t)rA0 * HH + k0 + ac);
            unsigned d1 = (unsigned)__cvta_generic_to_shared(&sm[SA_IDX(st, s, ar + 64, ac)]);
            CP16(d1, As[s] + (size_t)rA1 * HH + k0 + ac);
            unsigned e0 = (unsigned)__cvta_generic_to_shared(&sm[SB_IDX(st, s, br, bc)]);
            CP16(e0, Bs[s] + (size_t)(k0 + br) * HH + bn + bc);
            unsigned e1 = (unsigned)__cvta_generic_to_shared(&sm[SB_IDX(st, s, br + 16, bc)]);
            CP16(e1, Bs[s] + (size_t)(k0 + br + 16) * HH + bn + bc);
        }
        asm volatile("cp.async.commit_group;\n" ::: "memory");
    };

    load_stage(0, 0);

    const int lrow = lane & 15, lcol = (lane >> 4) * 8;
    const int NCH = HH / KC;   // 24

    for (int c = 0; c < NCH; c++) {
        asm volatile("cp.async.wait_group 0;\n" ::: "memory");
        __syncthreads();
        if (c + 1 < NCH) load_stage((c + 1) & 1, (c + 1) * KC);
        const int st = c & 1;

        #pragma unroll
        for (int ks = 0; ks < 2; ks++) {
            const int kb = ks * 16;
            unsigned a[2][2][4];   // [split][mtile][4]
            #pragma unroll
            for (int mt = 0; mt < 2; mt++)
                #pragma unroll
                for (int s = 0; s < 2; s++)
                    ldsm4(a[s][mt], &sm[SA_IDX(st, s, warp_m * 32 + mt * 16 + lrow, kb + lcol)]);
            #pragma unroll
            for (int g = 0; g < 4; g++) {
                unsigned bh[4], bl[4];
                ldsm4t(bh, &sm[SB_IDX(st, 0, kb + lrow, warp_n * 64 + g * 16 + lcol)]);
                ldsm4t(bl, &sm[SB_IDX(st, 1, kb + lrow, warp_n * 64 + g * 16 + lcol)]);
                #pragma unroll
                for (int mt = 0; mt < 2; mt++) {
                    mma16816(acc[mt][2*g],   a[0][mt], bh);
                    mma16816(acc[mt][2*g],   a[0][mt], bl);
                    mma16816(acc[mt][2*g],   a[1][mt], bh);
                    mma16816(acc[mt][2*g+1], a[0][mt], bh + 2);
                    mma16816(acc[mt][2*g+1], a[0][mt], bl + 2);
                    mma16816(acc[mt][2*g+1], a[1][mt], bh + 2);
                }
            }
        }
    }

    // ---- epilogue: bias add, fp32 store, optional fused score partials ----
    const int er = bm + warp_m * 32 + (lane >> 2);
    const int ec = bn + warp_n * 64 + (lane & 3) * 2;
    float p1[2][2] = {}, p2[2][2] = {};   // [mt][rowhalf]
    #pragma unroll
    for (int mt = 0; mt < 2; mt++)
        #pragma unroll
        for (int nt = 0; nt < 8; nt++) {
            int r = er + mt * 16;
            int cc = ec + nt * 8;
            float b0 = bias[cc], b1 = bias[cc + 1];
            float v00 = acc[mt][nt][0] + b0, v01 = acc[mt][nt][1] + b1;
            float v10 = acc[mt][nt][2] + b0, v11 = acc[mt][nt][3] + b1;
            if (r < M) {
                C[(size_t)r * HH + cc]     = v00;
                C[(size_t)r * HH + cc + 1] = v01;
            }
            if (r + 8 < M) {
                C[(size_t)(r + 8) * HH + cc]     = v10;
                C[(size_t)(r + 8) * HH + cc + 1] = v11;
            }
            if (avec) {
                float au0 = avec[cc], au1 = avec[cc + 1];
                float av0 = avec[HH + cc], av1 = avec[HH + cc + 1];
                p1[mt][0] += v00 * au0 + v01 * au1;
                p2[mt][0] += v00 * av0 + v01 * av1;
                p1[mt][1] += v10 * au0 + v11 * au1;
                p2[mt][1] += v10 * av0 + v11 * av1;
            }
        }
    if (avec) {
        #pragma unroll
        for (int mt = 0; mt < 2; mt++)
            #pragma unroll
            for (int h = 0; h < 2; h++) {
                #pragma unroll
                for (int o = 1; o <= 2; o <<= 1) {
                    p1[mt][h] += __shfl_xor_sync(~0u, p1[mt][h], o);
                    p2[mt][h] += __shfl_xor_sync(~0u, p2[mt][h], o);
                }
            }
        if ((lane & 3) == 0) {
            int slot = blockIdx.x * 2 + warp_n;
            #pragma unroll
            for (int mt = 0; mt < 2; mt++)
                #pragma unroll
                for (int h = 0; h < 2; h++) {
                    int r = er + mt * 16 + h * 8;
                    if (r < M) {
                        g_sp1[(size_t)slot * MTOT + r] = p1[mt][h];
                        g_sp2[(size_t)slot * MTOT + r] = p2[mt][h];
                    }
                }
        }
    }
}

// -- 3) fused GAT tail: reduce partials, masked softmax, apply (f32x2), elu -
__global__ __launch_bounds__(256) void gat_apply_kernel(
    const float* __restrict__ Wh, const int* __restrict__ adj,
    const float* __restrict__ ab,
    const float* __restrict__ resid, float* __restrict__ out_f32,
    __nv_bfloat16* __restrict__ hi, __nv_bfloat16* __restrict__ lo)
{
    int b = blockIdx.y, ch = blockIdx.x;       // 6 chunks of 128 cols
    __shared__ float att_s[NN * NN];           // 10 KB
    __shared__ float whs[NN][128];             // 25.6 KB
    __shared__ float asrc_s[NN], adst_s[NN];
    int t = threadIdx.x;
    int lane = t & 31, w = t >> 5;

    // load Wh chunk
    const float* whb = Wh + (size_t)b * NN * HH + ch * 128;
    for (int idx = t; idx < NN * 32; idx += 256) {
        int r = idx >> 5, c = (idx & 31) * 4;
        *(float4*)&whs[r][c] = *(const float4*)(whb + (size_t)r * HH + c);
    }
    // reduce the 12 score partials
    if (t < 2 * NN) {
        int i = t % NN;
        const float* sp = (t < NN) ? g_sp1 : g_sp2;
        float s = 0.f;
        #pragma unroll
        for (int c = 0; c < 12; c++) s += sp[(size_t)c * MTOT + b * NN + i];
        ((t < NN) ? asrc_s : adst_s)[i] = s;
    }
    __syncthreads();

    // masked softmax rows -> att_s (one warp per row)
    float abv = *ab;
    for (int i = w; i < NN; i += 8) {
        float ai = asrc_s[i];
        const int* adjr = adj + ((size_t)b * NN + i) * NN;
        int j2 = lane + 32;
        float v0 = ai + adst_s[lane] + abv;
        v0 = v0 >= 0.f ? v0 : 0.3f * v0;
        float e0 = (adjr[lane] > 0) ? v0 : -1e30f;
        float e1 = -1e30f;
        if (j2 < NN) {
            float v1 = ai + adst_s[j2] + abv;
            v1 = v1 >= 0.f ? v1 : 0.3f * v1;
            e1 = (adjr[j2] > 0) ? v1 : -1e30f;
        }
        float m = fmaxf(e0, e1);
        #pragma unroll
        for (int o = 16; o; o >>= 1) m = fmaxf(m, __shfl_xor_sync(~0u, m, o));
        float x0 = expf(e0 - m);
        float x1 = (j2 < NN) ? expf(e1 - m) : 0.f;
        float s = x0 + x1;
        #pragma unroll
        for (int o = 16; o; o >>= 1) s += __shfl_xor_sync(~0u, s, o);
        float inv = 1.f / s;
        att_s[i * NN + lane] = x0 * inv;
        if (j2 < NN) att_s[i * NN + j2] = x1 * inv;
    }
    __syncthreads();

    // apply: each thread owns a column PAIR; 4 rows per pass, packed f32x2 FMA
    int p = t & 63;                // column pair (cols 2p, 2p+1)
    int rg = t >> 6;               // 0..3
    int r0 = rg * 13;
    int r1 = min(r0 + 13, NN);     // 13,13,13,11 rows
    for (int i = r0; i < r1; i += 4) {
        int i1 = min(i + 1, NN - 1), i2 = min(i + 2, NN - 1), i3 = min(i + 3, NN - 1);
        unsigned long long a0 = 0, a1 = 0, a2 = 0, a3 = 0;
        #pragma unroll 10
        for (int j = 0; j < NN; j++) {
            unsigned long long wv = *(const unsigned long long*)&whs[j][2 * p];
            float t0 = att_s[i  * NN + j];
            float t1 = att_s[i1 * NN + j];
            float t2 = att_s[i2 * NN + j];
            float t3 = att_s[i3 * NN + j];
            ffma2(a0, pack2(t0, t0), wv);
            ffma2(a1, pack2(t1, t1), wv);
            ffma2(a2, pack2(t2, t2), wv);
            ffma2(a3, pack2(t3, t3), wv);
        }
        unsigned long long accs[4] = {a0, a1, a2, a3};
        #pragma unroll
        for (int k = 0; k < 4; k++) {
            int row = i + k;
            if (row >= r1) break;
            float vx, vy;
            unpack2(accs[k], vx, vy);
            vx = vx > 0.f ? vx : expm1f(vx);
            vy = vy > 0.f ? vy : expm1f(vy);
            size_t off = ((size_t)b * NN + row) * HH + ch * 128 + 2 * p;
            if (resid) { vx += resid[off]; vy += resid[off + 1]; }
            if (out_f32) { out_f32[off] = vx; out_f32[off + 1] = vy; }
            split1(vx, hi[off], lo[off]);
            split1(vy, hi[off + 1], lo[off + 1]);
        }
    }
}

// -------- 5) attention pooling -> fp32 D -----------------------------------
__global__ void pool_kernel(const float* __restrict__ T,
                            const float* __restrict__ v,
                            const float* __restrict__ Hres,
                            float* __restrict__ D)
{
    int b = blockIdx.x;
    int t = threadIdx.x, lane = t & 31, w = t >> 5;
    __shared__ float sc[NN];
    for (int n = w; n < NN; n += 8) {
        const float4* row = (const float4*)(T + ((size_t)b * NN + n) * HH);
        float s = 0.f;
        for (int c2 = lane; c2 < HH / 4; c2 += 32) {
            float4 x = row[c2];
            float4 u = ((const float4*)v)[c2];
            s += tanhf(x.x) * u.x + tanhf(x.y) * u.y +
                 tanhf(x.z) * u.z + tanhf(x.w) * u.w;
        }
        #pragma unroll
        for (int o = 16; o; o >>= 1) s += __shfl_xor_sync(~0u, s, o);
        if (lane == 0) sc[n] = s;
    }
    __syncthreads();
    if (t == 0) {
        float m = -1e30f;
        for (int n = 0; n < NN; n++) m = fmaxf(m, sc[n]);
        float s = 0.f;
        for (int n = 0; n < NN; n++) { sc[n] = expf(sc[n] - m); s += sc[n]; }
        float inv = 1.f / s;
        for (int n = 0; n < NN; n++) sc[n] *= inv;
    }
    __syncthreads();
    for (int h = t; h < HH; h += 256) {
        float acc = 0.f;
        #pragma unroll 5
        for (int n = 0; n < NN; n++)
            acc = fmaf(sc[n], Hres[((size_t)b * NN + n) * HH + h], acc);
        D[(size_t)b * HH + h] = acc;
    }
}

// -------- 6) final linear: out[64,768] = D @ Wl + bl (fp32, wide grid) -----
__global__ __launch_bounds__(128) void final_linear_kernel(
    const float* __restrict__ D, const float* __restrict__ W,
    const float* __restrict__ bias, float* __restrict__ out)
{
    int b = blockIdx.y;
    int o = blockIdx.x * 128 + threadIdx.x;
    __shared__ float Ds[HH];
    for (int i = threadIdx.x; i < HH; i += 128)
        Ds[i] = D[(size_t)b * HH + i];
    __syncthreads();
    float acc = 0.f;
    #pragma unroll 8
    for (int h = 0; h < HH; h++)
        acc = fmaf(Ds[h], W[(size_t)h * OO + o], acc);
    out[(size_t)b * OO + o] = acc + bias[o];
}

// ---------------- launch ----------------------------------------------------
extern "C" void kernel_launch(void* const* d_in, const int* in_sizes, int n_in,
                              void* d_out, int out_size)
{
    const float* emb = (const float*)d_in[0];
    const int*   ids = (const int*)  d_in[1];
    const int*   adj = (const int*)  d_in[2];
    const float* W1  = (const float*)d_in[3];
    const float* b1  = (const float*)d_in[4];
    const float* a1  = (const float*)d_in[5];
    const float* ab1 = (const float*)d_in[6];
    const float* W2  = (const float*)d_in[7];
    const float* b2  = (const float*)d_in[8];
    const float* a2  = (const float*)d_in[9];
    const float* ab2 = (const float*)d_in[10];
    const float* Wa  = (const float*)d_in[11];
    const float* ba  = (const float*)d_in[12];
    const float* v   = (const float*)d_in[13];
    const float* Wl  = (const float*)d_in[14];
    const float* bl  = (const float*)d_in[15];
    float* out = (float*)d_out;

    void *pX, *pWh, *pHres, *pT, *pD, *pAh, *pAl, *pBh, *pBl;
    cudaGetSymbolAddress(&pX, g_X);
    cudaGetSymbolAddress(&pWh, g_Wh);
    cudaGetSymbolAddress(&pHres, g_Hres);
    cudaGetSymbolAddress(&pT, g_T);
    cudaGetSymbolAddress(&pD, g_D);
    cudaGetSymbolAddress(&pAh, g_Ah);
    cudaGetSymbolAddress(&pAl, g_Al);
    cudaGetSymbolAddress(&pBh, g_Bh);
    cudaGetSymbolAddress(&pBl, g_Bl);
    float* X    = (float*)pX;
    float* Wh   = (float*)pWh;
    float* Hres = (float*)pHres;
    float* T    = (float*)pT;
    float* D    = (float*)pD;
    __nv_bfloat16* Ah = (__nv_bfloat16*)pAh;
    __nv_bfloat16* Al = (__nv_bfloat16*)pAl;
    __nv_bfloat16* Bh = (__nv_bfloat16*)pBh;
    __nv_bfloat16* Bl = (__nv_bfloat16*)pBl;
    const size_t WSZ = (size_t)HH * HH;

    cudaFuncSetAttribute(gemm_bf16x3,
                         cudaFuncAttributeMaxDynamicSharedMemorySize, SMEM_BYTES);

    dim3 ggemm(HH / 128, MTOT / 128);   // (6, 25) = 150 CTAs, 2/SM resident
    dim3 gapply(HH / 128, BB);          // (6, 64)
    dim3 gsplitw((HH * HH / 4 + 255) / 256, 3);
    dim3 gfinal(OO / 128, BB);          // (6, 64)

    // 0) weights -> bf16 splits (W1,W2,Wa)
    split_weights_kernel<<<gsplitw, 256>>>(W1, W2, Wa);
    // 1) gather + PE (+ split of X)
    gather_pe_kernel<<<MTOT, HH / 4>>>(emb, ids);
    // 2) Wh1 = X @ W1 + b1  (+ fused a1 score partials)
    gemm_bf16x3<<<ggemm, 256, SMEM_BYTES>>>(Ah, Al, Bh, Bl, b1, Wh, MTOT, a1);
    // 3) GAT layer 1 tail: softmax + apply (elu) -> split(H1)
    gat_apply_kernel<<<gapply, 256>>>(Wh, adj, ab1, nullptr, nullptr, Ah, Al);
    // 4) Wh2 = H1 @ W2 + b2 (+ fused a2 score partials)
    gemm_bf16x3<<<ggemm, 256, SMEM_BYTES>>>(Ah, Al, Bh + WSZ, Bl + WSZ, b2, Wh, MTOT, a2);
    // 5) GAT layer 2 tail: softmax + apply (elu + residual X) -> Hres + split
    gat_apply_kernel<<<gapply, 256>>>(Wh, adj, ab2, X, Hres, Ah, Al);
    // 6) T = Hres @ Wa + ba
    gemm_bf16x3<<<ggemm, 256, SMEM_BYTES>>>(Ah, Al, Bh + 2*WSZ, Bl + 2*WSZ, ba, T, MTOT, nullptr);
    // 7) attention pooling -> fp32 D
    pool_kernel<<<BB, 256>>>(T, v, Hres, D);
    // 8) out = D @ Wl + bl (fp32, wide grid)
    final_linear_kernel<<<gfinal, 128>>>(D, Wl, bl, out);
}